// round 2
// baseline (speedup 1.0000x reference)
#include <cuda_runtime.h>
#include <cstdint>

#define NN   100000
#define NE   1600000
#define F    64
#define HID  64
#define H2   128

// ---------------- device scratch (no allocs allowed) ----------------
__device__ __align__(16) float g_h0[(size_t)NN * HID];     // x @ W_conv
__device__ __align__(16) float g_agg[(size_t)NN * HID];    // aggregated messages
__device__ float g_dinv[NN];
__device__ int   g_deg[NN];

// ---------------- K1: h0 = x @ W_conv  (100000x64 @ 64x64) ----------------
__global__ void k_gemm1(const float* __restrict__ x, const float* __restrict__ W,
                        float* __restrict__ h0) {
    __shared__ __align__(16) float Ws[64 * 64];
    __shared__ float xs[64 * 65];               // pad to 65 -> conflict-free rows

    int t = threadIdx.x;
    for (int i = t; i < 64 * 64; i += 256) Ws[i] = W[i];

    int row0 = blockIdx.x * 64;
    for (int i = t; i < 64 * 16; i += 256) {
        int r = i >> 4, c4 = i & 15;
        int gr = row0 + r;
        float4 v = make_float4(0.f, 0.f, 0.f, 0.f);
        if (gr < NN) v = ((const float4*)x)[(size_t)gr * 16 + c4];
        float* p = &xs[r * 65 + c4 * 4];
        p[0] = v.x; p[1] = v.y; p[2] = v.z; p[3] = v.w;
    }
    __syncthreads();

    int tx = t & 15, ty = t >> 4;               // cols 4*tx, rows 4*ty
    float acc[4][4];
#pragma unroll
    for (int i = 0; i < 4; i++)
#pragma unroll
        for (int j = 0; j < 4; j++) acc[i][j] = 0.f;

#pragma unroll 4
    for (int k = 0; k < 64; k++) {
        float4 wv = *(const float4*)&Ws[k * 64 + 4 * tx];
#pragma unroll
        for (int i = 0; i < 4; i++) {
            float xv = xs[(4 * ty + i) * 65 + k];
            acc[i][0] += xv * wv.x;
            acc[i][1] += xv * wv.y;
            acc[i][2] += xv * wv.z;
            acc[i][3] += xv * wv.w;
        }
    }

#pragma unroll
    for (int i = 0; i < 4; i++) {
        int gr = row0 + 4 * ty + i;
        if (gr < NN) {
            float4 o = make_float4(acc[i][0], acc[i][1], acc[i][2], acc[i][3]);
            ((float4*)h0)[(size_t)gr * 16 + tx] = o;
        }
    }
}

// ---------------- K2: degree over dst (self loop added in k_init) -----------
__global__ void k_deg(const int* __restrict__ ei) {
    int e = blockIdx.x * blockDim.x + threadIdx.x;
    if (e < NE) {
        int dst = ei[NE + e];
        atomicAdd(&g_deg[dst], 1);
    }
}

// ---------------- K3: dinv + init agg with self-loop term -------------------
// agg[i][:] = h0[i][:] * dinv[i]^2   (also stores dinv)
__global__ void k_init(void) {
    int idx = blockIdx.x * blockDim.x + threadIdx.x;   // NN*16 float4 units
    if (idx >= NN * 16) return;
    int i = idx >> 4, c4 = idx & 15;
    float d = rsqrtf((float)g_deg[i] + 1.0f);          // deg includes self loop
    if (c4 == 0) g_dinv[i] = d;
    float n = d * d;
    float4 v = ((const float4*)g_h0)[idx];
    v.x *= n; v.y *= n; v.z *= n; v.w *= n;
    ((float4*)g_agg)[idx] = v;
}

// ---------------- K4: edge scatter  agg[dst] += h0[src]*dinv[src]*dinv[dst] --
// 2 edges per warp; 16 lanes x float4 per edge; vector red to L2.
__global__ void k_scatter(const int* __restrict__ ei) {
    int gwarp = (blockIdx.x * blockDim.x + threadIdx.x) >> 5;
    int lane  = threadIdx.x & 31;
    int sub   = lane >> 4;          // which of the 2 edges
    int c4    = lane & 15;          // float4 chunk within feature row
    int e = gwarp * 2 + sub;
    if (e >= NE) return;
    int src = ei[e];
    int dst = ei[NE + e];
    float nrm = g_dinv[src] * g_dinv[dst];
    float4 v = ((const float4*)g_h0)[(size_t)src * 16 + c4];
    v.x *= nrm; v.y *= nrm; v.z *= nrm; v.w *= nrm;
    float* p = g_agg + ((size_t)dst * 64 + c4 * 4);
    asm volatile("red.global.add.v4.f32 [%0], {%1,%2,%3,%4};"
                 :: "l"(p), "f"(v.x), "f"(v.y), "f"(v.z), "f"(v.w) : "memory");
}

// ---------------- K5: fused bias + ReLU + LayerNorm + GEMM2(64->128) + ReLU --
__global__ void k_epi(const float* __restrict__ bconv, const float* __restrict__ gamma,
                      const float* __restrict__ beta, const float* __restrict__ W1,
                      const float* __restrict__ b1, float* __restrict__ out) {
    __shared__ __align__(16) float W1s[64 * 128];
    __shared__ float b1s[128], bcs[64], gs[64], bs[64];
    __shared__ float vbuf[8][64];

    int t = threadIdx.x, lane = t & 31, w = t >> 5;
    for (int i = t; i < 64 * 128; i += 256) W1s[i] = W1[i];
    if (t < 128) b1s[t] = b1[t];
    if (t < 64) { bcs[t] = bconv[t]; gs[t] = gamma[t]; bs[t] = beta[t]; }
    __syncthreads();

    for (int node = blockIdx.x * 8 + w; node < NN; node += gridDim.x * 8) {
        float2 a = ((const float2*)g_agg)[(size_t)node * 32 + lane];
        a.x = fmaxf(a.x + bcs[2 * lane], 0.f);
        a.y = fmaxf(a.y + bcs[2 * lane + 1], 0.f);

        float s = a.x + a.y;
        float ss = a.x * a.x + a.y * a.y;
#pragma unroll
        for (int o = 16; o; o >>= 1) {
            s  += __shfl_xor_sync(0xffffffffu, s, o);
            ss += __shfl_xor_sync(0xffffffffu, ss, o);
        }
        float mu = s * (1.0f / 64.0f);
        float var = ss * (1.0f / 64.0f) - mu * mu;
        float r = rsqrtf(var + 1e-5f);

        vbuf[w][2 * lane]     = (a.x - mu) * r * gs[2 * lane]     + bs[2 * lane];
        vbuf[w][2 * lane + 1] = (a.y - mu) * r * gs[2 * lane + 1] + bs[2 * lane + 1];
        __syncwarp();

        float a0 = b1s[4 * lane], a1 = b1s[4 * lane + 1];
        float a2 = b1s[4 * lane + 2], a3 = b1s[4 * lane + 3];
#pragma unroll 8
        for (int k = 0; k < 64; k++) {
            float vk = vbuf[w][k];
            float4 wv = *(const float4*)&W1s[k * 128 + 4 * lane];
            a0 += vk * wv.x; a1 += vk * wv.y; a2 += vk * wv.z; a3 += vk * wv.w;
        }
        float4 o4 = make_float4(fmaxf(a0, 0.f), fmaxf(a1, 0.f),
                                fmaxf(a2, 0.f), fmaxf(a3, 0.f));
        ((float4*)out)[(size_t)node * 32 + lane] = o4;
        __syncwarp();
    }
}

// ---------------- edge_index tail variants ----------------
__global__ void k_edge_f32(const int* __restrict__ ei, float* __restrict__ o) {
    int i = blockIdx.x * blockDim.x + threadIdx.x;
    if (i < 2 * NE) o[i] = (float)ei[i];
}
__global__ void k_edge_i64(const int* __restrict__ ei, long long* __restrict__ o) {
    int i = blockIdx.x * blockDim.x + threadIdx.x;
    if (i < 2 * NE) o[i] = (long long)ei[i];
}

// ---------------- launch ----------------
extern "C" void kernel_launch(void* const* d_in, const int* in_sizes, int n_in,
                              void* d_out, int out_size) {
    const float* x      = (const float*)d_in[0];
    const int*   ei     = (const int*)d_in[1];     // int32 (JAX x64 disabled)
    const float* W_conv = (const float*)d_in[2];
    const float* b_conv = (const float*)d_in[3];
    const float* gamma  = (const float*)d_in[4];
    const float* beta   = (const float*)d_in[5];
    const float* W1     = (const float*)d_in[6];
    const float* b1     = (const float*)d_in[7];
    float* out = (float*)d_out;

    void* degp = nullptr;
    cudaGetSymbolAddress(&degp, g_deg);
    cudaMemsetAsync(degp, 0, NN * sizeof(int));

    {   // K1
        float* h0p; cudaGetSymbolAddress((void**)&h0p, g_h0);
        k_gemm1<<<(NN + 63) / 64, 256>>>(x, W_conv, h0p);
    }
    k_deg<<<(NE + 255) / 256, 256>>>(ei);
    k_init<<<(NN * 16 + 255) / 256, 256>>>();
    k_scatter<<<(NE + 15) / 16, 256>>>(ei);          // 16 edges / block
    k_epi<<<888, 256>>>(b_conv, gamma, beta, W1, b1, out);

    // tuple tail: edge_index pass-through
    long long n_h = (long long)NN * H2;              // 12,800,000
    long long rem = (long long)out_size - n_h;
    if (rem >= (long long)4 * NE) {
        // tail holds int64 raw (6.4M f32 words = 2*NE int64)
        k_edge_i64<<<(2 * NE + 255) / 256, 256>>>(ei, (long long*)(out + n_h));
    } else if (rem >= (long long)2 * NE) {
        // tail holds edge_index values widened/cast to f32 (exact: < 2^24)
        k_edge_f32<<<(2 * NE + 255) / 256, 256>>>(ei, out + n_h);
    }
}

// round 5
// speedup vs baseline: 1.0739x; 1.0739x over previous
#include <cuda_runtime.h>
#include <cstdint>

#define NN   100000
#define NE   1600000
#define HID  64
#define H2   128

typedef unsigned long long ull;

// ---------------- device scratch ----------------
__device__ __align__(16) float g_h0[(size_t)NN * HID];     // x @ W_conv
__device__ __align__(16) float g_agg[(size_t)NN * HID];    // aggregated messages
__device__ float g_dinv[NN];
__device__ int   g_deg[NN];

// ---------------- packed fp32x2 helpers ----------------
__device__ __forceinline__ ull fma2(ull a, ull b, ull c) {
    ull d;
    asm("fma.rn.f32x2 %0, %1, %2, %3;" : "=l"(d) : "l"(a), "l"(b), "l"(c));
    return d;
}
__device__ __forceinline__ ull pack2(float lo, float hi) {
    ull d;
    asm("mov.b64 %0, {%1, %2};" : "=l"(d) : "f"(lo), "f"(hi));
    return d;
}
__device__ __forceinline__ float lohisum(ull a) {
    float lo, hi;
    asm("mov.b64 {%0, %1}, %2;" : "=f"(lo), "=f"(hi) : "l"(a));
    return lo + hi;
}

// ---------------- K1: degree + edge_index tail (single pass over ei) --------
__global__ void k_deg_tail(const int* __restrict__ ei, float* __restrict__ tail,
                           int mode) {
    int i = blockIdx.x * blockDim.x + threadIdx.x;
    if (i >= 2 * NE) return;
    int v = ei[i];
    if (i >= NE) atomicAdd(&g_deg[v], 1);
    if (mode == 2)      ((long long*)tail)[i] = (long long)v;  // raw int64 tail
    else if (mode == 1) tail[i] = (float)v;                    // f32-cast tail
}

// ---------------- K2: gemm1 + init fused ------------------------------------
// h0 = x @ W_conv; dinv = rsqrt(deg+1); agg = h0 * dinv^2 (self-loop term).
// k-paired f32x2: acc.lo = even-k partials, acc.hi = odd-k partials.
__global__ void k_gemm1(const float* __restrict__ x, const float* __restrict__ W) {
    __shared__ __align__(16) ull Wp[32 * 64];   // (W[2t,c], W[2t+1,c])
    __shared__ __align__(16) ull xp[64 * 33];   // (x[r,2t], x[r,2t+1]), pad 33

    int t = threadIdx.x;
    for (int i = t; i < 32 * 64; i += 256) {
        int tt = i >> 6, c = i & 63;
        Wp[i] = pack2(W[(2 * tt) * 64 + c], W[(2 * tt + 1) * 64 + c]);
    }
    int row0 = blockIdx.x * 64;
    for (int i = t; i < 64 * 16; i += 256) {
        int r = i >> 4, c4 = i & 15;
        int gr = row0 + r;
        float4 v = make_float4(0.f, 0.f, 0.f, 0.f);
        if (gr < NN) v = ((const float4*)x)[(size_t)gr * 16 + c4];
        xp[r * 33 + 2 * c4]     = pack2(v.x, v.y);
        xp[r * 33 + 2 * c4 + 1] = pack2(v.z, v.w);
    }
    __syncthreads();

    int tx = t & 15, ty = t >> 4;               // cols 4*tx.., rows 4*ty..
    ull acc[4][4];
#pragma unroll
    for (int i = 0; i < 4; i++)
#pragma unroll
        for (int j = 0; j < 4; j++) acc[i][j] = 0ull;

#pragma unroll 8
    for (int tt = 0; tt < 32; tt++) {
        ulonglong2 wA = *(const ulonglong2*)&Wp[tt * 64 + 4 * tx];
        ulonglong2 wB = *(const ulonglong2*)&Wp[tt * 64 + 4 * tx + 2];
#pragma unroll
        for (int i = 0; i < 4; i++) {
            ull xv = xp[(4 * ty + i) * 33 + tt];
            acc[i][0] = fma2(xv, wA.x, acc[i][0]);
            acc[i][1] = fma2(xv, wA.y, acc[i][1]);
            acc[i][2] = fma2(xv, wB.x, acc[i][2]);
            acc[i][3] = fma2(xv, wB.y, acc[i][3]);
        }
    }

#pragma unroll
    for (int i = 0; i < 4; i++) {
        int gr = row0 + 4 * ty + i;
        if (gr < NN) {
            float d = rsqrtf((float)g_deg[gr] + 1.0f);   // deg incl. self loop
            if (tx == 0) g_dinv[gr] = d;                 // one writer per row
            float n2 = d * d;
            float4 o = make_float4(lohisum(acc[i][0]), lohisum(acc[i][1]),
                                   lohisum(acc[i][2]), lohisum(acc[i][3]));
            ((float4*)g_h0)[(size_t)gr * 16 + tx] = o;
            float4 s = make_float4(o.x * n2, o.y * n2, o.z * n2, o.w * n2);
            ((float4*)g_agg)[(size_t)gr * 16 + tx] = s;
        }
    }
}

// ---------------- K3: edge scatter (warp-batched) ---------------------------
// Each warp: 32 edges. Coalesced ei loads + one dinv-gather pair per edge,
// staged in smem; then 2 edges/iter, 16 lanes x float4 each, red.v4 to L2.
__global__ void k_scatter(const int* __restrict__ ei) {
    __shared__ int   sS[8][32];
    __shared__ int   sD[8][32];
    __shared__ float sN[8][32];

    int t = threadIdx.x, lane = t & 31, w = t >> 5;
    int base = (blockIdx.x * 8 + w) * 32;       // NE = 50000 warps * 32 exactly

    int src = ei[base + lane];
    int dst = ei[NE + base + lane];
    sS[w][lane] = src;
    sD[w][lane] = dst;
    sN[w][lane] = g_dinv[src] * g_dinv[dst];
    __syncwarp();

    int sub = lane >> 4;                        // which of the 2 edges this iter
    int c4  = lane & 15;                        // float4 chunk in feature row
#pragma unroll 4
    for (int j = 0; j < 16; j++) {
        int e = 2 * j + sub;
        int s = sS[w][e];
        int d = sD[w][e];
        float n = sN[w][e];
        float4 v = ((const float4*)g_h0)[(size_t)s * 16 + c4];
        v.x *= n; v.y *= n; v.z *= n; v.w *= n;
        float* p = g_agg + ((size_t)d * 64 + c4 * 4);
        asm volatile("red.global.add.v4.f32 [%0], {%1,%2,%3,%4};"
                     :: "l"(p), "f"(v.x), "f"(v.y), "f"(v.z), "f"(v.w) : "memory");
    }
}

// ---------------- K4: fused bias+ReLU+LN + GEMM2(64->128) + ReLU ------------
// 2 nodes per warp; W1 pre-packed in smem as k-pairs; f32x2 accumulate.
__global__ void k_epi(const float* __restrict__ bconv, const float* __restrict__ gamma,
                      const float* __restrict__ beta, const float* __restrict__ W1,
                      const float* __restrict__ b1, float* __restrict__ out) {
    __shared__ __align__(16) ull W1p[32 * 128];   // (W1[2t,j], W1[2t+1,j]) 32KB
    __shared__ __align__(16) ull vbufd[8][2][32];
    __shared__ float b1s[128];
    __shared__ float2 bc2[32], g2[32], be2[32];

    int t = threadIdx.x, lane = t & 31, w = t >> 5;
    for (int i = t; i < 32 * 128; i += 256) {
        int tt = i >> 7, j = i & 127;
        W1p[i] = pack2(W1[(2 * tt) * 128 + j], W1[(2 * tt + 1) * 128 + j]);
    }
    if (t < 128) b1s[t] = b1[t];
    if (t < 32) {
        bc2[t] = ((const float2*)bconv)[t];
        g2[t]  = ((const float2*)gamma)[t];
        be2[t] = ((const float2*)beta)[t];
    }
    __syncthreads();

    float2 bc = bc2[lane], gg = g2[lane], bb = be2[lane];
    float4 b1v = *(const float4*)&b1s[4 * lane];

    for (int n0 = blockIdx.x * 16 + w * 2; n0 + 1 < NN; n0 += gridDim.x * 16) {
        // --- LN for nodes n0 and n0+1 ---
        float2 a0 = ((const float2*)g_agg)[(size_t)n0 * 32 + lane];
        float2 a1 = ((const float2*)g_agg)[(size_t)(n0 + 1) * 32 + lane];
        a0.x = fmaxf(a0.x + bc.x, 0.f); a0.y = fmaxf(a0.y + bc.y, 0.f);
        a1.x = fmaxf(a1.x + bc.x, 0.f); a1.y = fmaxf(a1.y + bc.y, 0.f);

        float s0 = a0.x + a0.y, q0 = a0.x * a0.x + a0.y * a0.y;
        float s1 = a1.x + a1.y, q1 = a1.x * a1.x + a1.y * a1.y;
#pragma unroll
        for (int o = 16; o; o >>= 1) {
            s0 += __shfl_xor_sync(0xffffffffu, s0, o);
            q0 += __shfl_xor_sync(0xffffffffu, q0, o);
            s1 += __shfl_xor_sync(0xffffffffu, s1, o);
            q1 += __shfl_xor_sync(0xffffffffu, q1, o);
        }
        float mu0 = s0 * (1.f / 64.f), r0 = rsqrtf(q0 * (1.f / 64.f) - mu0 * mu0 + 1e-5f);
        float mu1 = s1 * (1.f / 64.f), r1 = rsqrtf(q1 * (1.f / 64.f) - mu1 * mu1 + 1e-5f);

        vbufd[w][0][lane] = pack2((a0.x - mu0) * r0 * gg.x + bb.x,
                                  (a0.y - mu0) * r0 * gg.y + bb.y);
        vbufd[w][1][lane] = pack2((a1.x - mu1) * r1 * gg.x + bb.x,
                                  (a1.y - mu1) * r1 * gg.y + bb.y);
        __syncwarp();

        // --- GEMM2: 4 outputs/lane/node, k-paired f32x2 ---
        ull c00 = 0, c01 = 0, c02 = 0, c03 = 0;
        ull c10 = 0, c11 = 0, c12 = 0, c13 = 0;
#pragma unroll 8
        for (int tt = 0; tt < 32; tt++) {
            ulonglong2 wA = *(const ulonglong2*)&W1p[tt * 128 + 4 * lane];
            ulonglong2 wB = *(const ulonglong2*)&W1p[tt * 128 + 4 * lane + 2];
            ull v0 = vbufd[w][0][tt];
            ull v1 = vbufd[w][1][tt];
            c00 = fma2(v0, wA.x, c00); c01 = fma2(v0, wA.y, c01);
            c02 = fma2(v0, wB.x, c02); c03 = fma2(v0, wB.y, c03);
            c10 = fma2(v1, wA.x, c10); c11 = fma2(v1, wA.y, c11);
            c12 = fma2(v1, wB.x, c12); c13 = fma2(v1, wB.y, c13);
        }
        float4 o0 = make_float4(fmaxf(lohisum(c00) + b1v.x, 0.f),
                                fmaxf(lohisum(c01) + b1v.y, 0.f),
                                fmaxf(lohisum(c02) + b1v.z, 0.f),
                                fmaxf(lohisum(c03) + b1v.w, 0.f));
        float4 o1 = make_float4(fmaxf(lohisum(c10) + b1v.x, 0.f),
                                fmaxf(lohisum(c11) + b1v.y, 0.f),
                                fmaxf(lohisum(c12) + b1v.z, 0.f),
                                fmaxf(lohisum(c13) + b1v.w, 0.f));
        ((float4*)out)[(size_t)n0 * 32 + lane] = o0;
        ((float4*)out)[(size_t)(n0 + 1) * 32 + lane] = o1;
        __syncwarp();
    }
}

// ---------------- launch ----------------
extern "C" void kernel_launch(void* const* d_in, const int* in_sizes, int n_in,
                              void* d_out, int out_size) {
    const float* x      = (const float*)d_in[0];
    const int*   ei     = (const int*)d_in[1];     // int32
    const float* W_conv = (const float*)d_in[2];
    const float* b_conv = (const float*)d_in[3];
    const float* gamma  = (const float*)d_in[4];
    const float* beta   = (const float*)d_in[5];
    const float* W1     = (const float*)d_in[6];
    const float* b1     = (const float*)d_in[7];
    float* out = (float*)d_out;

    void* degp = nullptr;
    cudaGetSymbolAddress(&degp, g_deg);
    cudaMemsetAsync(degp, 0, NN * sizeof(int));

    long long n_h = (long long)NN * H2;            // 12,800,000
    long long rem = (long long)out_size - n_h;
    int mode = (rem >= (long long)4 * NE) ? 2 : (rem >= (long long)2 * NE) ? 1 : 0;

    k_deg_tail<<<(2 * NE + 255) / 256, 256>>>(ei, out + n_h, mode);
    k_gemm1<<<(NN + 63) / 64, 256>>>(x, W_conv);
    k_scatter<<<NE / (8 * 32), 256>>>(ei);         // 6250 blocks, exact
    k_epi<<<296, 256>>>(b_conv, gamma, beta, W1, b1, out);
}

// round 7
// speedup vs baseline: 1.3581x; 1.2647x over previous
#include <cuda_runtime.h>
#include <cstdint>

#define NN   100000
#define NE   1600000
#define HID  64
#define H2   128

typedef unsigned long long ull;

// ---------------- device scratch ----------------
__device__ __align__(16) float g_h0[(size_t)NN * HID];     // x @ W_conv
__device__ __align__(16) float g_agg[(size_t)NN * HID];    // aggregated messages
__device__ float g_dinv[NN];
__device__ int   g_deg[NN];

// ---------------- packed fp32x2 helpers ----------------
__device__ __forceinline__ ull fma2(ull a, ull b, ull c) {
    ull d;
    asm("fma.rn.f32x2 %0, %1, %2, %3;" : "=l"(d) : "l"(a), "l"(b), "l"(c));
    return d;
}
__device__ __forceinline__ ull pack2(float lo, float hi) {
    ull d;
    asm("mov.b64 %0, {%1, %2};" : "=l"(d) : "f"(lo), "f"(hi));
    return d;
}
__device__ __forceinline__ float lohisum(ull a) {
    float lo, hi;
    asm("mov.b64 {%0, %1}, %2;" : "=f"(lo), "=f"(hi) : "l"(a));
    return lo + hi;
}

// ---------------- K1: degree + edge_index tail (vectorized single pass) -----
__global__ void k_deg_tail(const int* __restrict__ ei, float* __restrict__ tail,
                           int mode) {
    int i4 = blockIdx.x * blockDim.x + threadIdx.x;    // (2*NE)/4 int4 units
    if (i4 >= (2 * NE) / 4) return;
    int4 v = ((const int4*)ei)[i4];
    int base = i4 * 4;
    if (base >= NE) {                                  // dst half -> degree
        atomicAdd(&g_deg[v.x], 1);
        atomicAdd(&g_deg[v.y], 1);
        atomicAdd(&g_deg[v.z], 1);
        atomicAdd(&g_deg[v.w], 1);
    }
    if (mode == 1) {
        float4 f = make_float4((float)v.x, (float)v.y, (float)v.z, (float)v.w);
        ((float4*)tail)[i4] = f;
    } else if (mode == 2) {
        longlong2 a = make_longlong2((long long)v.x, (long long)v.y);
        longlong2 b = make_longlong2((long long)v.z, (long long)v.w);
        ((longlong2*)tail)[i4 * 2]     = a;
        ((longlong2*)tail)[i4 * 2 + 1] = b;
    }
}

// ---------------- K2: gemm1 + init fused ------------------------------------
// h0 = x @ W_conv; dinv = rsqrt(deg+1); agg = h0 * dinv^2 (self-loop term).
__global__ void k_gemm1(const float* __restrict__ x, const float* __restrict__ W) {
    __shared__ __align__(16) ull Wp[32 * 64];   // (W[2t,c], W[2t+1,c])
    __shared__ __align__(16) ull xp[64 * 34];   // (x[r,2t], x[r,2t+1]), even pad

    int t = threadIdx.x;
    for (int i = t; i < 32 * 64; i += 256) {
        int tt = i >> 6, c = i & 63;
        Wp[i] = pack2(W[(2 * tt) * 64 + c], W[(2 * tt + 1) * 64 + c]);
    }
    int row0 = blockIdx.x * 64;
    for (int i = t; i < 64 * 16; i += 256) {
        int r = i >> 4, c4 = i & 15;
        int gr = row0 + r;
        float4 v = make_float4(0.f, 0.f, 0.f, 0.f);
        if (gr < NN) v = ((const float4*)x)[(size_t)gr * 16 + c4];
        xp[r * 34 + 2 * c4]     = pack2(v.x, v.y);
        xp[r * 34 + 2 * c4 + 1] = pack2(v.z, v.w);
    }
    __syncthreads();

    int tx = t & 15, ty = t >> 4;               // cols 4*tx.., rows 4*ty..
    ull acc[4][4];
#pragma unroll
    for (int i = 0; i < 4; i++)
#pragma unroll
        for (int j = 0; j < 4; j++) acc[i][j] = 0ull;

#pragma unroll 8
    for (int tt = 0; tt < 32; tt++) {
        ulonglong2 wA = *(const ulonglong2*)&Wp[tt * 64 + 4 * tx];
        ulonglong2 wB = *(const ulonglong2*)&Wp[tt * 64 + 4 * tx + 2];
#pragma unroll
        for (int i = 0; i < 4; i++) {
            ull xv = xp[(4 * ty + i) * 34 + tt];
            acc[i][0] = fma2(xv, wA.x, acc[i][0]);
            acc[i][1] = fma2(xv, wA.y, acc[i][1]);
            acc[i][2] = fma2(xv, wB.x, acc[i][2]);
            acc[i][3] = fma2(xv, wB.y, acc[i][3]);
        }
    }

#pragma unroll
    for (int i = 0; i < 4; i++) {
        int gr = row0 + 4 * ty + i;
        if (gr < NN) {
            float d = rsqrtf((float)g_deg[gr] + 1.0f);   // deg incl. self loop
            if (tx == 0) g_dinv[gr] = d;                 // one writer per row
            float n2 = d * d;
            float4 o = make_float4(lohisum(acc[i][0]), lohisum(acc[i][1]),
                                   lohisum(acc[i][2]), lohisum(acc[i][3]));
            ((float4*)g_h0)[(size_t)gr * 16 + tx] = o;
            float4 s = make_float4(o.x * n2, o.y * n2, o.z * n2, o.w * n2);
            ((float4*)g_agg)[(size_t)gr * 16 + tx] = s;
        }
    }
}

// ---------------- K3: edge scatter (warp-batched) ---------------------------
__global__ void k_scatter(const int* __restrict__ ei) {
    __shared__ int   sS[8][32];
    __shared__ int   sD[8][32];
    __shared__ float sN[8][32];

    int t = threadIdx.x, lane = t & 31, w = t >> 5;
    int base = (blockIdx.x * 8 + w) * 32;       // NE = 50000 warps * 32 exactly

    int src = ei[base + lane];
    int dst = ei[NE + base + lane];
    sS[w][lane] = src;
    sD[w][lane] = dst;
    sN[w][lane] = g_dinv[src] * g_dinv[dst];
    __syncwarp();

    int sub = lane >> 4;
    int c4  = lane & 15;
#pragma unroll 4
    for (int j = 0; j < 16; j++) {
        int e = 2 * j + sub;
        int s = sS[w][e];
        int d = sD[w][e];
        float n = sN[w][e];
        float4 v = ((const float4*)g_h0)[(size_t)s * 16 + c4];
        v.x *= n; v.y *= n; v.z *= n; v.w *= n;
        float* p = g_agg + ((size_t)d * 64 + c4 * 4);
        asm volatile("red.global.add.v4.f32 [%0], {%1,%2,%3,%4};"
                     :: "l"(p), "f"(v.x), "f"(v.y), "f"(v.z), "f"(v.w) : "memory");
    }
}

// ---------------- K4: fused bias+ReLU+LN + block-tiled GEMM2 + ReLU ---------
// Block = 64 nodes. LN phase writes normalized vectors TRANSPOSED to smem
// (vs[kpair][row], pad 66). GEMM phase: 2 column passes of 64 cols each;
// W1p holds only the current pass's columns (16 KB), restaged between passes.
// Thread tile 4 rows x 4 cols; lane mapping keeps each LDS.128 within 1-2
// 128B wavefronts (4-8 distinct addresses).
#define VS_LD 66
__global__ void __launch_bounds__(256) k_epi(
        const float* __restrict__ bconv, const float* __restrict__ gamma,
        const float* __restrict__ beta, const float* __restrict__ W1,
        const float* __restrict__ b1, float* __restrict__ out) {
    __shared__ __align__(16) ull W1p[32 * 64];      // [kpair][localcol], 16KB
    __shared__ __align__(16) ull vs[32 * VS_LD];    // [kpair][row], 16.5KB
    __shared__ float b1s[128];
    __shared__ float2 bc2[32], g2[32], be2[32];

    int t = threadIdx.x, lane = t & 31, w = t >> 5;
    if (t < 128) b1s[t] = b1[t];
    if (t < 32) {
        bc2[t] = ((const float2*)bconv)[t];
        g2[t]  = ((const float2*)gamma)[t];
        be2[t] = ((const float2*)beta)[t];
    }
    __syncthreads();

    int node0 = blockIdx.x * 64;
    float2 bc = bc2[lane], gg = g2[lane], bb = be2[lane];

    // --- LN phase: warp w handles rows 8w .. 8w+7 ---
#pragma unroll
    for (int s = 0; s < 8; s++) {
        int row = 8 * w + s;
        int node = node0 + row;
        if (node < NN) {
            float2 a = ((const float2*)g_agg)[(size_t)node * 32 + lane];
            a.x = fmaxf(a.x + bc.x, 0.f);
            a.y = fmaxf(a.y + bc.y, 0.f);
            float sm = a.x + a.y, sq = a.x * a.x + a.y * a.y;
#pragma unroll
            for (int o = 16; o; o >>= 1) {
                sm += __shfl_xor_sync(0xffffffffu, sm, o);
                sq += __shfl_xor_sync(0xffffffffu, sq, o);
            }
            float mu = sm * (1.f / 64.f);
            float r = rsqrtf(sq * (1.f / 64.f) - mu * mu + 1e-5f);
            vs[lane * VS_LD + row] = pack2((a.x - mu) * r * gg.x + bb.x,
                                           (a.y - mu) * r * gg.y + bb.y);
        }
    }

    // --- GEMM phase: 2 passes of 64 output columns ---
    int rb = 32 * (w >> 2) + 4 * (lane >> 2);   // local row base (0..60)
    int cg = 16 * (w & 3) + 4 * (lane & 3);     // local col base (0..60)

#pragma unroll
    for (int pass = 0; pass < 2; pass++) {
        __syncthreads();                         // vs ready / prev pass done
        for (int i = t; i < 32 * 64; i += 256) { // stage this pass's W1 cols
            int tt = i >> 6, c = i & 63;
            W1p[i] = pack2(W1[(2 * tt) * 128 + pass * 64 + c],
                           W1[(2 * tt + 1) * 128 + pass * 64 + c]);
        }
        __syncthreads();

        ull acc[4][4];
#pragma unroll
        for (int r = 0; r < 4; r++)
#pragma unroll
            for (int c = 0; c < 4; c++) acc[r][c] = 0ull;

#pragma unroll 4
        for (int tt = 0; tt < 32; tt++) {
            ulonglong2 w0 = *(const ulonglong2*)&W1p[tt * 64 + cg];
            ulonglong2 w1 = *(const ulonglong2*)&W1p[tt * 64 + cg + 2];
            ulonglong2 v0 = *(const ulonglong2*)&vs[tt * VS_LD + rb];
            ulonglong2 v1 = *(const ulonglong2*)&vs[tt * VS_LD + rb + 2];
            ull vr0 = v0.x, vr1 = v0.y, vr2 = v1.x, vr3 = v1.y;
            acc[0][0] = fma2(vr0, w0.x, acc[0][0]);
            acc[0][1] = fma2(vr0, w0.y, acc[0][1]);
            acc[0][2] = fma2(vr0, w1.x, acc[0][2]);
            acc[0][3] = fma2(vr0, w1.y, acc[0][3]);
            acc[1][0] = fma2(vr1, w0.x, acc[1][0]);
            acc[1][1] = fma2(vr1, w0.y, acc[1][1]);
            acc[1][2] = fma2(vr1, w1.x, acc[1][2]);
            acc[1][3] = fma2(vr1, w1.y, acc[1][3]);
            acc[2][0] = fma2(vr2, w0.x, acc[2][0]);
            acc[2][1] = fma2(vr2, w0.y, acc[2][1]);
            acc[2][2] = fma2(vr2, w1.x, acc[2][2]);
            acc[2][3] = fma2(vr2, w1.y, acc[2][3]);
            acc[3][0] = fma2(vr3, w0.x, acc[3][0]);
            acc[3][1] = fma2(vr3, w0.y, acc[3][1]);
            acc[3][2] = fma2(vr3, w1.x, acc[3][2]);
            acc[3][3] = fma2(vr3, w1.y, acc[3][3]);
        }

        int cb = pass * 64 + cg;
        float4 bv = *(const float4*)&b1s[cb];
#pragma unroll
        for (int r = 0; r < 4; r++) {
            int node = node0 + rb + r;
            if (node < NN) {
                float4 o = make_float4(fmaxf(lohisum(acc[r][0]) + bv.x, 0.f),
                                       fmaxf(lohisum(acc[r][1]) + bv.y, 0.f),
                                       fmaxf(lohisum(acc[r][2]) + bv.z, 0.f),
                                       fmaxf(lohisum(acc[r][3]) + bv.w, 0.f));
                *(float4*)&out[(size_t)node * 128 + cb] = o;
            }
        }
    }
}

// ---------------- launch ----------------
extern "C" void kernel_launch(void* const* d_in, const int* in_sizes, int n_in,
                              void* d_out, int out_size) {
    const float* x      = (const float*)d_in[0];
    const int*   ei     = (const int*)d_in[1];     // int32
    const float* W_conv = (const float*)d_in[2];
    const float* b_conv = (const float*)d_in[3];
    const float* gamma  = (const float*)d_in[4];
    const float* beta   = (const float*)d_in[5];
    const float* W1     = (const float*)d_in[6];
    const float* b1     = (const float*)d_in[7];
    float* out = (float*)d_out;

    void* degp = nullptr;
    cudaGetSymbolAddress(&degp, g_deg);
    cudaMemsetAsync(degp, 0, NN * sizeof(int));

    long long n_h = (long long)NN * H2;            // 12,800,000
    long long rem = (long long)out_size - n_h;
    int mode = (rem >= (long long)4 * NE) ? 2 : (rem >= (long long)2 * NE) ? 1 : 0;

    k_deg_tail<<<((2 * NE / 4) + 255) / 256, 256>>>(ei, out + n_h, mode);
    k_gemm1<<<(NN + 63) / 64, 256>>>(x, W_conv);
    k_scatter<<<NE / (8 * 32), 256>>>(ei);         // 6250 blocks, exact
    k_epi<<<(NN + 63) / 64, 256>>>(b_conv, gamma, beta, W1, b1, out);
}

// round 8
// speedup vs baseline: 1.4116x; 1.0394x over previous
#include <cuda_runtime.h>
#include <cstdint>

#define NN   100000
#define NE   1600000
#define HID  64
#define H2   128

typedef unsigned long long ull;

// ---------------- device scratch ----------------
__device__ __align__(16) float g_h0[(size_t)NN * HID];     // x @ W_conv
__device__ __align__(16) float g_agg[(size_t)NN * HID];    // aggregated messages
__device__ float g_dinv[NN];
__device__ int   g_deg[NN];

// ---------------- packed fp32x2 helpers ----------------
__device__ __forceinline__ ull fma2(ull a, ull b, ull c) {
    ull d;
    asm("fma.rn.f32x2 %0, %1, %2, %3;" : "=l"(d) : "l"(a), "l"(b), "l"(c));
    return d;
}
__device__ __forceinline__ ull pack2(float lo, float hi) {
    ull d;
    asm("mov.b64 %0, {%1, %2};" : "=l"(d) : "f"(lo), "f"(hi));
    return d;
}
__device__ __forceinline__ float lohisum(ull a) {
    float lo, hi;
    asm("mov.b64 {%0, %1}, %2;" : "=f"(lo), "=f"(hi) : "l"(a));
    return lo + hi;
}

// ---------------- K1: degree + edge_index tail (vectorized single pass) -----
__global__ void k_deg_tail(const int* __restrict__ ei, float* __restrict__ tail,
                           int mode) {
    int i4 = blockIdx.x * blockDim.x + threadIdx.x;    // (2*NE)/4 int4 units
    if (i4 >= (2 * NE) / 4) return;
    int4 v = ((const int4*)ei)[i4];
    int base = i4 * 4;
    if (base >= NE) {                                  // dst half -> degree
        atomicAdd(&g_deg[v.x], 1);
        atomicAdd(&g_deg[v.y], 1);
        atomicAdd(&g_deg[v.z], 1);
        atomicAdd(&g_deg[v.w], 1);
    }
    if (mode == 1) {
        float4 f = make_float4((float)v.x, (float)v.y, (float)v.z, (float)v.w);
        ((float4*)tail)[i4] = f;
    } else if (mode == 2) {
        longlong2 a = make_longlong2((long long)v.x, (long long)v.y);
        longlong2 b = make_longlong2((long long)v.z, (long long)v.w);
        ((longlong2*)tail)[i4 * 2]     = a;
        ((longlong2*)tail)[i4 * 2 + 1] = b;
    }
}

// ---------------- K2: gemm1 + init fused ------------------------------------
// h0 = x @ W_conv; dinv = rsqrt(deg+1); agg = h0 * dinv^2 (self-loop term).
// Thread cols {2tx,2tx+1, 32+2tx,32+2tx+1}: W-loads contiguous 256B/warp.
__global__ void k_gemm1(const float* __restrict__ x, const float* __restrict__ W) {
    __shared__ __align__(16) ull Wp[32 * 64];   // [kpair][col] packed
    __shared__ __align__(16) ull xp[64 * 34];   // [row][kpair], even pad

    int t = threadIdx.x;
    for (int i = t; i < 32 * 64; i += 256) {
        int tt = i >> 6, c = i & 63;
        Wp[i] = pack2(W[(2 * tt) * 64 + c], W[(2 * tt + 1) * 64 + c]);
    }
    int row0 = blockIdx.x * 64;
    for (int i = t; i < 64 * 16; i += 256) {
        int r = i >> 4, c4 = i & 15;
        int gr = row0 + r;
        float4 v = make_float4(0.f, 0.f, 0.f, 0.f);
        if (gr < NN) v = ((const float4*)x)[(size_t)gr * 16 + c4];
        xp[r * 34 + 2 * c4]     = pack2(v.x, v.y);
        xp[r * 34 + 2 * c4 + 1] = pack2(v.z, v.w);
    }
    __syncthreads();

    int tx = t & 15, ty = t >> 4;               // rows 4*ty.., cols {2tx,32+2tx}
    ull acc[4][4];
#pragma unroll
    for (int i = 0; i < 4; i++)
#pragma unroll
        for (int j = 0; j < 4; j++) acc[i][j] = 0ull;

#pragma unroll 8
    for (int tt = 0; tt < 32; tt++) {
        ulonglong2 wA = *(const ulonglong2*)&Wp[tt * 64 + 2 * tx];       // cols 2tx,2tx+1
        ulonglong2 wB = *(const ulonglong2*)&Wp[tt * 64 + 32 + 2 * tx];  // cols 32+2tx,+1
#pragma unroll
        for (int i = 0; i < 4; i++) {
            ull xv = xp[(4 * ty + i) * 34 + tt];
            acc[i][0] = fma2(xv, wA.x, acc[i][0]);
            acc[i][1] = fma2(xv, wA.y, acc[i][1]);
            acc[i][2] = fma2(xv, wB.x, acc[i][2]);
            acc[i][3] = fma2(xv, wB.y, acc[i][3]);
        }
    }

#pragma unroll
    for (int i = 0; i < 4; i++) {
        int gr = row0 + 4 * ty + i;
        if (gr < NN) {
            float d = rsqrtf((float)g_deg[gr] + 1.0f);   // deg incl. self loop
            if (tx == 0) g_dinv[gr] = d;                 // one writer per row
            float n2 = d * d;
            float2 oA = make_float2(lohisum(acc[i][0]), lohisum(acc[i][1]));
            float2 oB = make_float2(lohisum(acc[i][2]), lohisum(acc[i][3]));
            ((float2*)g_h0)[(size_t)gr * 32 + tx]      = oA;
            ((float2*)g_h0)[(size_t)gr * 32 + 16 + tx] = oB;
            float2 sA = make_float2(oA.x * n2, oA.y * n2);
            float2 sB = make_float2(oB.x * n2, oB.y * n2);
            ((float2*)g_agg)[(size_t)gr * 32 + tx]      = sA;
            ((float2*)g_agg)[(size_t)gr * 32 + 16 + tx] = sB;
        }
    }
}

// ---------------- K3: edge scatter (warp-batched) ---------------------------
__global__ void k_scatter(const int* __restrict__ ei) {
    __shared__ int   sS[8][32];
    __shared__ int   sD[8][32];
    __shared__ float sN[8][32];

    int t = threadIdx.x, lane = t & 31, w = t >> 5;
    int base = (blockIdx.x * 8 + w) * 32;       // NE = 50000 warps * 32 exactly

    int src = ei[base + lane];
    int dst = ei[NE + base + lane];
    sS[w][lane] = src;
    sD[w][lane] = dst;
    sN[w][lane] = g_dinv[src] * g_dinv[dst];
    __syncwarp();

    int sub = lane >> 4;
    int c4  = lane & 15;
#pragma unroll 4
    for (int j = 0; j < 16; j++) {
        int e = 2 * j + sub;
        int s = sS[w][e];
        int d = sD[w][e];
        float n = sN[w][e];
        float4 v = ((const float4*)g_h0)[(size_t)s * 16 + c4];
        v.x *= n; v.y *= n; v.z *= n; v.w *= n;
        float* p = g_agg + ((size_t)d * 64 + c4 * 4);
        asm volatile("red.global.add.v4.f32 [%0], {%1,%2,%3,%4};"
                     :: "l"(p), "f"(v.x), "f"(v.y), "f"(v.z), "f"(v.w) : "memory");
    }
}

// ---------------- K4: fused bias+ReLU+LN + block-tiled GEMM2 + ReLU ---------
// Block = 64 nodes. vs[kpair][row] transposed in smem. GEMM: 2 column passes;
// W1p holds current pass cols (16KB). Thread rows {r0,r0+1,r0+16,r0+17} with
// r0 = 32*(w>>2)+2*(lane>>2): every v-LDS.128 is 128B contiguous per warp
// (1 wavefront, conflict-free); W loads 1 wf (4 addrs in 128B).
#define VS_LD 66
__global__ void __launch_bounds__(256, 4) k_epi(
        const float* __restrict__ bconv, const float* __restrict__ gamma,
        const float* __restrict__ beta, const float* __restrict__ W1,
        const float* __restrict__ b1, float* __restrict__ out) {
    __shared__ __align__(16) ull W1p[32 * 64];      // [kpair][localcol], 16KB
    __shared__ __align__(16) ull vs[32 * VS_LD];    // [kpair][row], 16.5KB
    __shared__ float b1s[128];
    __shared__ float2 bc2[32], g2[32], be2[32];

    int t = threadIdx.x, lane = t & 31, w = t >> 5;
    if (t < 128) b1s[t] = b1[t];
    if (t < 32) {
        bc2[t] = ((const float2*)bconv)[t];
        g2[t]  = ((const float2*)gamma)[t];
        be2[t] = ((const float2*)beta)[t];
    }
    __syncthreads();

    int node0 = blockIdx.x * 64;
    float2 bc = bc2[lane], gg = g2[lane], bb = be2[lane];

    // --- LN phase: warp w handles rows 8w .. 8w+7 ---
#pragma unroll
    for (int s = 0; s < 8; s++) {
        int row = 8 * w + s;
        int node = node0 + row;
        if (node < NN) {
            float2 a = ((const float2*)g_agg)[(size_t)node * 32 + lane];
            a.x = fmaxf(a.x + bc.x, 0.f);
            a.y = fmaxf(a.y + bc.y, 0.f);
            float sm = a.x + a.y, sq = a.x * a.x + a.y * a.y;
#pragma unroll
            for (int o = 16; o; o >>= 1) {
                sm += __shfl_xor_sync(0xffffffffu, sm, o);
                sq += __shfl_xor_sync(0xffffffffu, sq, o);
            }
            float mu = sm * (1.f / 64.f);
            float r = rsqrtf(sq * (1.f / 64.f) - mu * mu + 1e-5f);
            vs[lane * VS_LD + row] = pack2((a.x - mu) * r * gg.x + bb.x,
                                           (a.y - mu) * r * gg.y + bb.y);
        }
    }

    // --- GEMM phase: 2 passes of 64 output columns ---
    int r0 = 32 * (w >> 2) + 2 * (lane >> 2);   // rows r0,r0+1,r0+16,r0+17
    int cg = 16 * (w & 3) + 4 * (lane & 3);     // local col base

#pragma unroll
    for (int pass = 0; pass < 2; pass++) {
        __syncthreads();                         // vs ready / prev pass done
        for (int i = t; i < 32 * 64; i += 256) { // stage this pass's W1 cols
            int tt = i >> 6, c = i & 63;
            W1p[i] = pack2(W1[(2 * tt) * 128 + pass * 64 + c],
                           W1[(2 * tt + 1) * 128 + pass * 64 + c]);
        }
        __syncthreads();

        ull acc[4][4];
#pragma unroll
        for (int r = 0; r < 4; r++)
#pragma unroll
            for (int c = 0; c < 4; c++) acc[r][c] = 0ull;

#pragma unroll 4
        for (int tt = 0; tt < 32; tt++) {
            ulonglong2 w0 = *(const ulonglong2*)&W1p[tt * 64 + cg];
            ulonglong2 w1 = *(const ulonglong2*)&W1p[tt * 64 + cg + 2];
            ulonglong2 v0 = *(const ulonglong2*)&vs[tt * VS_LD + r0];       // r0,r0+1
            ulonglong2 v1 = *(const ulonglong2*)&vs[tt * VS_LD + r0 + 16];  // +16,+17
            ull vr0 = v0.x, vr1 = v0.y, vr2 = v1.x, vr3 = v1.y;
            acc[0][0] = fma2(vr0, w0.x, acc[0][0]);
            acc[0][1] = fma2(vr0, w0.y, acc[0][1]);
            acc[0][2] = fma2(vr0, w1.x, acc[0][2]);
            acc[0][3] = fma2(vr0, w1.y, acc[0][3]);
            acc[1][0] = fma2(vr1, w0.x, acc[1][0]);
            acc[1][1] = fma2(vr1, w0.y, acc[1][1]);
            acc[1][2] = fma2(vr1, w1.x, acc[1][2]);
            acc[1][3] = fma2(vr1, w1.y, acc[1][3]);
            acc[2][0] = fma2(vr2, w0.x, acc[2][0]);
            acc[2][1] = fma2(vr2, w0.y, acc[2][1]);
            acc[2][2] = fma2(vr2, w1.x, acc[2][2]);
            acc[2][3] = fma2(vr2, w1.y, acc[2][3]);
            acc[3][0] = fma2(vr3, w0.x, acc[3][0]);
            acc[3][1] = fma2(vr3, w0.y, acc[3][1]);
            acc[3][2] = fma2(vr3, w1.x, acc[3][2]);
            acc[3][3] = fma2(vr3, w1.y, acc[3][3]);
        }

        int cb = pass * 64 + cg;
        float4 bv = *(const float4*)&b1s[cb];
        int rows[4] = {r0, r0 + 1, r0 + 16, r0 + 17};
#pragma unroll
        for (int r = 0; r < 4; r++) {
            int node = node0 + rows[r];
            if (node < NN) {
                float4 o = make_float4(fmaxf(lohisum(acc[r][0]) + bv.x, 0.f),
                                       fmaxf(lohisum(acc[r][1]) + bv.y, 0.f),
                                       fmaxf(lohisum(acc[r][2]) + bv.z, 0.f),
                                       fmaxf(lohisum(acc[r][3]) + bv.w, 0.f));
                *(float4*)&out[(size_t)node * 128 + cb] = o;
            }
        }
    }
}

// ---------------- launch ----------------
extern "C" void kernel_launch(void* const* d_in, const int* in_sizes, int n_in,
                              void* d_out, int out_size) {
    const float* x      = (const float*)d_in[0];
    const int*   ei     = (const int*)d_in[1];     // int32
    const float* W_conv = (const float*)d_in[2];
    const float* b_conv = (const float*)d_in[3];
    const float* gamma  = (const float*)d_in[4];
    const float* beta   = (const float*)d_in[5];
    const float* W1     = (const float*)d_in[6];
    const float* b1     = (const float*)d_in[7];
    float* out = (float*)d_out;

    void* degp = nullptr;
    cudaGetSymbolAddress(&degp, g_deg);
    cudaMemsetAsync(degp, 0, NN * sizeof(int));

    long long n_h = (long long)NN * H2;            // 12,800,000
    long long rem = (long long)out_size - n_h;
    int mode = (rem >= (long long)4 * NE) ? 2 : (rem >= (long long)2 * NE) ? 1 : 0;

    k_deg_tail<<<((2 * NE / 4) + 255) / 256, 256>>>(ei, out + n_h, mode);
    k_gemm1<<<(NN + 63) / 64, 256>>>(x, W_conv);
    k_scatter<<<NE / (8 * 32), 256>>>(ei);         // 6250 blocks, exact
    k_epi<<<(NN + 63) / 64, 256>>>(b_conv, gamma, beta, W1, b1, out);
}

// round 10
// speedup vs baseline: 1.4378x; 1.0186x over previous
#include <cuda_runtime.h>
#include <cstdint>

#define NN   100000
#define NE   1600000
#define HID  64
#define H2   128

typedef unsigned long long ull;

// ---------------- device scratch ----------------
__device__ __align__(16) float g_h0[(size_t)NN * HID];     // x @ W_conv
__device__ __align__(16) float g_agg[(size_t)NN * HID];    // aggregated messages
__device__ float g_dinv[NN];
__device__ int   g_deg[NN];

// ---------------- packed fp32x2 helpers (gemm1) ----------------
__device__ __forceinline__ ull fma2(ull a, ull b, ull c) {
    ull d;
    asm("fma.rn.f32x2 %0, %1, %2, %3;" : "=l"(d) : "l"(a), "l"(b), "l"(c));
    return d;
}
__device__ __forceinline__ ull pack2(float lo, float hi) {
    ull d;
    asm("mov.b64 %0, {%1, %2};" : "=l"(d) : "f"(lo), "f"(hi));
    return d;
}
__device__ __forceinline__ float lohisum(ull a) {
    float lo, hi;
    asm("mov.b64 {%0, %1}, %2;" : "=f"(lo), "=f"(hi) : "l"(a));
    return lo + hi;
}

// ---------------- tf32 mma helpers ----------------
__device__ __forceinline__ uint32_t f2tf(float x) {
    uint32_t r;
    asm("cvt.rna.tf32.f32 %0, %1;" : "=r"(r) : "f"(x));
    return r;
}
__device__ __forceinline__ void tfsplit(float x, uint32_t& hi, uint32_t& lo) {
    hi = f2tf(x);
    lo = f2tf(x - __uint_as_float(hi));
}
__device__ __forceinline__ void mma_tf32(float* c, uint32_t a0, uint32_t a1,
                                         uint32_t a2, uint32_t a3,
                                         uint32_t b0, uint32_t b1) {
    asm("mma.sync.aligned.m16n8k8.row.col.f32.tf32.tf32.f32 "
        "{%0,%1,%2,%3}, {%4,%5,%6,%7}, {%8,%9}, {%0,%1,%2,%3};"
        : "+f"(c[0]), "+f"(c[1]), "+f"(c[2]), "+f"(c[3])
        : "r"(a0), "r"(a1), "r"(a2), "r"(a3), "r"(b0), "r"(b1));
}

// ---------------- K1: degree + edge_index tail (vectorized single pass) -----
__global__ void k_deg_tail(const int* __restrict__ ei, float* __restrict__ tail,
                           int mode) {
    int i4 = blockIdx.x * blockDim.x + threadIdx.x;    // (2*NE)/4 int4 units
    if (i4 >= (2 * NE) / 4) return;
    int4 v = ((const int4*)ei)[i4];
    int base = i4 * 4;
    if (base >= NE) {                                  // dst half -> degree
        atomicAdd(&g_deg[v.x], 1);
        atomicAdd(&g_deg[v.y], 1);
        atomicAdd(&g_deg[v.z], 1);
        atomicAdd(&g_deg[v.w], 1);
    }
    if (mode == 1) {
        float4 f = make_float4((float)v.x, (float)v.y, (float)v.z, (float)v.w);
        ((float4*)tail)[i4] = f;
    } else if (mode == 2) {
        longlong2 a = make_longlong2((long long)v.x, (long long)v.y);
        longlong2 b = make_longlong2((long long)v.z, (long long)v.w);
        ((longlong2*)tail)[i4 * 2]     = a;
        ((longlong2*)tail)[i4 * 2 + 1] = b;
    }
}

// ---------------- K2: gemm1 + init fused (unchanged from R8) ----------------
__global__ void k_gemm1(const float* __restrict__ x, const float* __restrict__ W) {
    __shared__ __align__(16) ull Wp[32 * 64];
    __shared__ __align__(16) ull xp[64 * 34];

    int t = threadIdx.x;
    for (int i = t; i < 32 * 64; i += 256) {
        int tt = i >> 6, c = i & 63;
        Wp[i] = pack2(W[(2 * tt) * 64 + c], W[(2 * tt + 1) * 64 + c]);
    }
    int row0 = blockIdx.x * 64;
    for (int i = t; i < 64 * 16; i += 256) {
        int r = i >> 4, c4 = i & 15;
        int gr = row0 + r;
        float4 v = make_float4(0.f, 0.f, 0.f, 0.f);
        if (gr < NN) v = ((const float4*)x)[(size_t)gr * 16 + c4];
        xp[r * 34 + 2 * c4]     = pack2(v.x, v.y);
        xp[r * 34 + 2 * c4 + 1] = pack2(v.z, v.w);
    }
    __syncthreads();

    int tx = t & 15, ty = t >> 4;
    ull acc[4][4];
#pragma unroll
    for (int i = 0; i < 4; i++)
#pragma unroll
        for (int j = 0; j < 4; j++) acc[i][j] = 0ull;

#pragma unroll 8
    for (int tt = 0; tt < 32; tt++) {
        ulonglong2 wA = *(const ulonglong2*)&Wp[tt * 64 + 2 * tx];
        ulonglong2 wB = *(const ulonglong2*)&Wp[tt * 64 + 32 + 2 * tx];
#pragma unroll
        for (int i = 0; i < 4; i++) {
            ull xv = xp[(4 * ty + i) * 34 + tt];
            acc[i][0] = fma2(xv, wA.x, acc[i][0]);
            acc[i][1] = fma2(xv, wA.y, acc[i][1]);
            acc[i][2] = fma2(xv, wB.x, acc[i][2]);
            acc[i][3] = fma2(xv, wB.y, acc[i][3]);
        }
    }

#pragma unroll
    for (int i = 0; i < 4; i++) {
        int gr = row0 + 4 * ty + i;
        if (gr < NN) {
            float d = rsqrtf((float)g_deg[gr] + 1.0f);
            if (tx == 0) g_dinv[gr] = d;
            float n2 = d * d;
            float2 oA = make_float2(lohisum(acc[i][0]), lohisum(acc[i][1]));
            float2 oB = make_float2(lohisum(acc[i][2]), lohisum(acc[i][3]));
            ((float2*)g_h0)[(size_t)gr * 32 + tx]      = oA;
            ((float2*)g_h0)[(size_t)gr * 32 + 16 + tx] = oB;
            float2 sA = make_float2(oA.x * n2, oA.y * n2);
            float2 sB = make_float2(oB.x * n2, oB.y * n2);
            ((float2*)g_agg)[(size_t)gr * 32 + tx]      = sA;
            ((float2*)g_agg)[(size_t)gr * 32 + 16 + tx] = sB;
        }
    }
}

// ---------------- K3: edge scatter (unchanged from R8) ----------------------
__global__ void k_scatter(const int* __restrict__ ei) {
    __shared__ int   sS[8][32];
    __shared__ int   sD[8][32];
    __shared__ float sN[8][32];

    int t = threadIdx.x, lane = t & 31, w = t >> 5;
    int base = (blockIdx.x * 8 + w) * 32;

    int src = ei[base + lane];
    int dst = ei[NE + base + lane];
    sS[w][lane] = src;
    sD[w][lane] = dst;
    sN[w][lane] = g_dinv[src] * g_dinv[dst];
    __syncwarp();

    int sub = lane >> 4;
    int c4  = lane & 15;
#pragma unroll 4
    for (int j = 0; j < 16; j++) {
        int e = 2 * j + sub;
        int s = sS[w][e];
        int d = sD[w][e];
        float n = sN[w][e];
        float4 v = ((const float4*)g_h0)[(size_t)s * 16 + c4];
        v.x *= n; v.y *= n; v.z *= n; v.w *= n;
        float* p = g_agg + ((size_t)d * 64 + c4 * 4);
        asm volatile("red.global.add.v4.f32 [%0], {%1,%2,%3,%4};"
                     :: "l"(p), "f"(v.x), "f"(v.y), "f"(v.z), "f"(v.w) : "memory");
    }
}

// ---------------- K4: bias+ReLU+LN + tensor-core GEMM2 (3xTF32) + ReLU ------
// Block = 64 nodes x 128 cols, 256 threads. LN writes v to vs[row][k] with
// XOR swizzle col^(4*(row&7)) -> conflict-free fragment loads AND stores.
// GEMM: mma.m16n8k8.tf32, warp tile 16 rows x 32 cols, 2 passes of 64 cols;
// W1 staged per pass in B-fragment order (W1f[kstep][nbG][lane] = {b0,b1}).
__global__ void __launch_bounds__(256) k_epi(
        const float* __restrict__ bconv, const float* __restrict__ gamma,
        const float* __restrict__ beta, const float* __restrict__ W1,
        const float* __restrict__ b1, float* __restrict__ out) {
    __shared__ __align__(16) float  vs[64 * 64];     // 16KB, swizzled
    __shared__ __align__(16) float2 W1f[8 * 8 * 32]; // 16KB, fragment order
    __shared__ float b1s[128];
    __shared__ float2 bc2[32], g2[32], be2[32];

    int t = threadIdx.x, lane = t & 31, w = t >> 5;
    if (t < 128) b1s[t] = b1[t];
    if (t < 32) {
        bc2[t] = ((const float2*)bconv)[t];
        g2[t]  = ((const float2*)gamma)[t];
        be2[t] = ((const float2*)beta)[t];
    }
    __syncthreads();

    int node0 = blockIdx.x * 64;

    // tail block: zero-fill vs so mma on invalid rows is well-defined
    if (node0 + 64 > NN) {
        for (int i = t; i < 64 * 64; i += 256) vs[i] = 0.f;
        __syncthreads();
    }

    float2 bc = bc2[lane], gg = g2[lane], bb = be2[lane];

    // --- LN phase: warp w -> rows 8w..8w+7 ---
#pragma unroll
    for (int s = 0; s < 8; s++) {
        int row = 8 * w + s;
        int node = node0 + row;
        if (node < NN) {
            float2 a = ((const float2*)g_agg)[(size_t)node * 32 + lane];
            a.x = fmaxf(a.x + bc.x, 0.f);
            a.y = fmaxf(a.y + bc.y, 0.f);
            float sm = a.x + a.y, sq = a.x * a.x + a.y * a.y;
#pragma unroll
            for (int o = 16; o; o >>= 1) {
                sm += __shfl_xor_sync(0xffffffffu, sm, o);
                sq += __shfl_xor_sync(0xffffffffu, sq, o);
            }
            float mu = sm * (1.f / 64.f);
            float r = rsqrtf(sq * (1.f / 64.f) - mu * mu + 1e-5f);
            float2 v = make_float2((a.x - mu) * r * gg.x + bb.x,
                                   (a.y - mu) * r * gg.y + bb.y);
            int sw = (2 * lane) ^ (4 * (row & 7));   // XOR keeps pair adjacent
            *(float2*)&vs[row * 64 + sw] = v;
        }
    }

    // --- GEMM phase ---
    int g  = lane >> 2;            // fragment groupID (0..7)
    int tg = lane & 3;             // threadID in group (0..3)
    int h  = w >> 2;               // col-half (0/1)
    int Gr = 16 * (w & 3);         // warp row base

#pragma unroll
    for (int pass = 0; pass < 2; pass++) {
        int pb = pass * 64;
        __syncthreads();           // vs ready / prev pass W1f done
        // stage W1 fragments: W1f[(ks*8+nbG)*32+lane] = {W1[k1][c], W1[k1+4][c]}
        for (int i = t; i < 2048; i += 256) {
            int ks  = i >> 8;
            int nbG = (i >> 5) & 7;
            int ln  = i & 31;
            int k1  = ks * 8 + (ln & 3);
            int c   = pb + nbG * 8 + (ln >> 2);
            W1f[i] = make_float2(W1[k1 * 128 + c], W1[(k1 + 4) * 128 + c]);
        }
        __syncthreads();

        float acc[4][4];
#pragma unroll
        for (int nb = 0; nb < 4; nb++)
#pragma unroll
            for (int i = 0; i < 4; i++) acc[nb][i] = 0.f;

#pragma unroll
        for (int ks = 0; ks < 8; ks++) {
            int kc0 = (ks * 8 + tg)     ^ (4 * g);
            int kc1 = (ks * 8 + tg + 4) ^ (4 * g);
            float af0 = vs[(Gr + g) * 64 + kc0];      // (row g,   col t)
            float af1 = vs[(Gr + g + 8) * 64 + kc0];  // (row g+8, col t)
            float af2 = vs[(Gr + g) * 64 + kc1];      // (row g,   col t+4)
            float af3 = vs[(Gr + g + 8) * 64 + kc1];  // (row g+8, col t+4)
            uint32_t ah0, al0, ah1, al1, ah2, al2, ah3, al3;
            tfsplit(af0, ah0, al0);
            tfsplit(af1, ah1, al1);
            tfsplit(af2, ah2, al2);
            tfsplit(af3, ah3, al3);
#pragma unroll
            for (int nb = 0; nb < 4; nb++) {
                float2 bbv = W1f[(ks * 8 + 4 * h + nb) * 32 + lane];
                uint32_t bh0, bl0, bh1, bl1;
                tfsplit(bbv.x, bh0, bl0);
                tfsplit(bbv.y, bh1, bl1);
                mma_tf32(acc[nb], ah0, ah1, ah2, ah3, bh0, bh1);
                mma_tf32(acc[nb], ah0, ah1, ah2, ah3, bl0, bl1);
                mma_tf32(acc[nb], al0, al1, al2, al3, bh0, bh1);
            }
        }

        // epilogue: bias + relu + store (c0,c1)->row g, (c2,c3)->row g+8
#pragma unroll
        for (int nb = 0; nb < 4; nb++) {
            int col = pb + (4 * h + nb) * 8 + 2 * tg;
            float bx = b1s[col], by = b1s[col + 1];
            int nA = node0 + Gr + g;
            int nB = nA + 8;
            if (nA < NN) {
                float2 o = make_float2(fmaxf(acc[nb][0] + bx, 0.f),
                                       fmaxf(acc[nb][1] + by, 0.f));
                *(float2*)&out[(size_t)nA * 128 + col] = o;
            }
            if (nB < NN) {
                float2 o = make_float2(fmaxf(acc[nb][2] + bx, 0.f),
                                       fmaxf(acc[nb][3] + by, 0.f));
                *(float2*)&out[(size_t)nB * 128 + col] = o;
            }
        }
    }
}

// ---------------- launch ----------------
extern "C" void kernel_launch(void* const* d_in, const int* in_sizes, int n_in,
                              void* d_out, int out_size) {
    const float* x      = (const float*)d_in[0];
    const int*   ei     = (const int*)d_in[1];     // int32
    const float* W_conv = (const float*)d_in[2];
    const float* b_conv = (const float*)d_in[3];
    const float* gamma  = (const float*)d_in[4];
    const float* beta   = (const float*)d_in[5];
    const float* W1     = (const float*)d_in[6];
    const float* b1     = (const float*)d_in[7];
    float* out = (float*)d_out;

    void* degp = nullptr;
    cudaGetSymbolAddress(&degp, g_deg);
    cudaMemsetAsync(degp, 0, NN * sizeof(int));

    long long n_h = (long long)NN * H2;            // 12,800,000
    long long rem = (long long)out_size - n_h;
    int mode = (rem >= (long long)4 * NE) ? 2 : (rem >= (long long)2 * NE) ? 1 : 0;

    k_deg_tail<<<((2 * NE / 4) + 255) / 256, 256>>>(ei, out + n_h, mode);
    k_gemm1<<<(NN + 63) / 64, 256>>>(x, W_conv);
    k_scatter<<<NE / (8 * 32), 256>>>(ei);         // 6250 blocks, exact
    k_epi<<<(NN + 63) / 64, 256>>>(b_conv, gamma, beta, W1, b1, out);
}

// round 11
// speedup vs baseline: 1.4692x; 1.0218x over previous
#include <cuda_runtime.h>
#include <cstdint>

#define NN   100000
#define NE   1600000
#define HID  64
#define H2   128

typedef unsigned long long ull;

// ---------------- device scratch ----------------
__device__ __align__(16) float g_h0[(size_t)NN * HID];     // x @ W_conv
__device__ __align__(16) float g_agg[(size_t)NN * HID];    // aggregated messages
__device__ float g_dinv[NN];
__device__ int   g_deg[NN];

// ---------------- packed fp32x2 helpers (gemm1) ----------------
__device__ __forceinline__ ull fma2(ull a, ull b, ull c) {
    ull d;
    asm("fma.rn.f32x2 %0, %1, %2, %3;" : "=l"(d) : "l"(a), "l"(b), "l"(c));
    return d;
}
__device__ __forceinline__ ull pack2(float lo, float hi) {
    ull d;
    asm("mov.b64 %0, {%1, %2};" : "=l"(d) : "f"(lo), "f"(hi));
    return d;
}
__device__ __forceinline__ float lohisum(ull a) {
    float lo, hi;
    asm("mov.b64 {%0, %1}, %2;" : "=f"(lo), "=f"(hi) : "l"(a));
    return lo + hi;
}

// ---------------- tf32 mma helpers ----------------
__device__ __forceinline__ uint32_t f2tf(float x) {
    uint32_t r;
    asm("cvt.rna.tf32.f32 %0, %1;" : "=r"(r) : "f"(x));
    return r;
}
__device__ __forceinline__ void tfsplit(float x, uint32_t& hi, uint32_t& lo) {
    hi = f2tf(x);
    lo = f2tf(x - __uint_as_float(hi));
}
__device__ __forceinline__ void mma_tf32(float* c, uint32_t a0, uint32_t a1,
                                         uint32_t a2, uint32_t a3,
                                         uint32_t b0, uint32_t b1) {
    asm("mma.sync.aligned.m16n8k8.row.col.f32.tf32.tf32.f32 "
        "{%0,%1,%2,%3}, {%4,%5,%6,%7}, {%8,%9}, {%0,%1,%2,%3};"
        : "+f"(c[0]), "+f"(c[1]), "+f"(c[2]), "+f"(c[3])
        : "r"(a0), "r"(a1), "r"(a2), "r"(a3), "r"(b0), "r"(b1));
}

// ---------------- K1: degree + edge_index tail (vectorized single pass) -----
__global__ void k_deg_tail(const int* __restrict__ ei, float* __restrict__ tail,
                           int mode) {
    int i4 = blockIdx.x * blockDim.x + threadIdx.x;    // (2*NE)/4 int4 units
    if (i4 >= (2 * NE) / 4) return;
    int4 v = ((const int4*)ei)[i4];
    int base = i4 * 4;
    if (base >= NE) {                                  // dst half -> degree
        atomicAdd(&g_deg[v.x], 1);
        atomicAdd(&g_deg[v.y], 1);
        atomicAdd(&g_deg[v.z], 1);
        atomicAdd(&g_deg[v.w], 1);
    }
    if (mode == 1) {
        float4 f = make_float4((float)v.x, (float)v.y, (float)v.z, (float)v.w);
        ((float4*)tail)[i4] = f;
    } else if (mode == 2) {
        longlong2 a = make_longlong2((long long)v.x, (long long)v.y);
        longlong2 b = make_longlong2((long long)v.z, (long long)v.w);
        ((longlong2*)tail)[i4 * 2]     = a;
        ((longlong2*)tail)[i4 * 2 + 1] = b;
    }
}

// ---------------- K2: gemm1 + init fused (unchanged) ------------------------
__global__ void k_gemm1(const float* __restrict__ x, const float* __restrict__ W) {
    __shared__ __align__(16) ull Wp[32 * 64];
    __shared__ __align__(16) ull xp[64 * 34];

    int t = threadIdx.x;
    for (int i = t; i < 32 * 64; i += 256) {
        int tt = i >> 6, c = i & 63;
        Wp[i] = pack2(W[(2 * tt) * 64 + c], W[(2 * tt + 1) * 64 + c]);
    }
    int row0 = blockIdx.x * 64;
    for (int i = t; i < 64 * 16; i += 256) {
        int r = i >> 4, c4 = i & 15;
        int gr = row0 + r;
        float4 v = make_float4(0.f, 0.f, 0.f, 0.f);
        if (gr < NN) v = ((const float4*)x)[(size_t)gr * 16 + c4];
        xp[r * 34 + 2 * c4]     = pack2(v.x, v.y);
        xp[r * 34 + 2 * c4 + 1] = pack2(v.z, v.w);
    }
    __syncthreads();

    int tx = t & 15, ty = t >> 4;
    ull acc[4][4];
#pragma unroll
    for (int i = 0; i < 4; i++)
#pragma unroll
        for (int j = 0; j < 4; j++) acc[i][j] = 0ull;

#pragma unroll 8
    for (int tt = 0; tt < 32; tt++) {
        ulonglong2 wA = *(const ulonglong2*)&Wp[tt * 64 + 2 * tx];
        ulonglong2 wB = *(const ulonglong2*)&Wp[tt * 64 + 32 + 2 * tx];
#pragma unroll
        for (int i = 0; i < 4; i++) {
            ull xv = xp[(4 * ty + i) * 34 + tt];
            acc[i][0] = fma2(xv, wA.x, acc[i][0]);
            acc[i][1] = fma2(xv, wA.y, acc[i][1]);
            acc[i][2] = fma2(xv, wB.x, acc[i][2]);
            acc[i][3] = fma2(xv, wB.y, acc[i][3]);
        }
    }

#pragma unroll
    for (int i = 0; i < 4; i++) {
        int gr = row0 + 4 * ty + i;
        if (gr < NN) {
            float d = rsqrtf((float)g_deg[gr] + 1.0f);
            if (tx == 0) g_dinv[gr] = d;
            float n2 = d * d;
            float2 oA = make_float2(lohisum(acc[i][0]), lohisum(acc[i][1]));
            float2 oB = make_float2(lohisum(acc[i][2]), lohisum(acc[i][3]));
            ((float2*)g_h0)[(size_t)gr * 32 + tx]      = oA;
            ((float2*)g_h0)[(size_t)gr * 32 + 16 + tx] = oB;
            float2 sA = make_float2(oA.x * n2, oA.y * n2);
            float2 sB = make_float2(oB.x * n2, oB.y * n2);
            ((float2*)g_agg)[(size_t)gr * 32 + tx]      = sA;
            ((float2*)g_agg)[(size_t)gr * 32 + 16 + tx] = sB;
        }
    }
}

// ---------------- K3: edge scatter (unchanged) ------------------------------
__global__ void k_scatter(const int* __restrict__ ei) {
    __shared__ int   sS[8][32];
    __shared__ int   sD[8][32];
    __shared__ float sN[8][32];

    int t = threadIdx.x, lane = t & 31, w = t >> 5;
    int base = (blockIdx.x * 8 + w) * 32;

    int src = ei[base + lane];
    int dst = ei[NE + base + lane];
    sS[w][lane] = src;
    sD[w][lane] = dst;
    sN[w][lane] = g_dinv[src] * g_dinv[dst];
    __syncwarp();

    int sub = lane >> 4;
    int c4  = lane & 15;
#pragma unroll 4
    for (int j = 0; j < 16; j++) {
        int e = 2 * j + sub;
        int s = sS[w][e];
        int d = sD[w][e];
        float n = sN[w][e];
        float4 v = ((const float4*)g_h0)[(size_t)s * 16 + c4];
        v.x *= n; v.y *= n; v.z *= n; v.w *= n;
        float* p = g_agg + ((size_t)d * 64 + c4 * 4);
        asm volatile("red.global.add.v4.f32 [%0], {%1,%2,%3,%4};"
                     :: "l"(p), "f"(v.x), "f"(v.y), "f"(v.z), "f"(v.w) : "memory");
    }
}

// ---------------- K4: bias+ReLU+LN + tensor GEMM2 (3xTF32, pre-split B) -----
// Block = 64 nodes x 128 cols. vs swizzled as before. B (W1) fragments are
// tf32-SPLIT AT STAGING into W1fh/W1fl -> zero cvt in the mma loop.
// Smem = 16KB + 16KB + 16KB = 49152 B exactly; biases/ln params via __ldg.
__global__ void __launch_bounds__(256) k_epi(
        const float* __restrict__ bconv, const float* __restrict__ gamma,
        const float* __restrict__ beta, const float* __restrict__ W1,
        const float* __restrict__ b1, float* __restrict__ out) {
    __shared__ __align__(16) float vs[64 * 64];      // 16KB, swizzled
    __shared__ __align__(16) uint2 W1fh[8 * 8 * 32]; // 16KB, hi fragments
    __shared__ __align__(16) uint2 W1fl[8 * 8 * 32]; // 16KB, lo fragments

    int t = threadIdx.x, lane = t & 31, w = t >> 5;
    int node0 = blockIdx.x * 64;

    // tail block: zero-fill vs so mma on invalid rows is well-defined
    if (node0 + 64 > NN) {
        for (int i = t; i < 64 * 64; i += 256) vs[i] = 0.f;
        __syncthreads();
    }

    float2 bc = __ldg((const float2*)bconv + lane);
    float2 gg = __ldg((const float2*)gamma + lane);
    float2 bb = __ldg((const float2*)beta + lane);

    // --- LN phase: warp w -> rows 8w..8w+7 ---
#pragma unroll
    for (int s = 0; s < 8; s++) {
        int row = 8 * w + s;
        int node = node0 + row;
        if (node < NN) {
            float2 a = ((const float2*)g_agg)[(size_t)node * 32 + lane];
            a.x = fmaxf(a.x + bc.x, 0.f);
            a.y = fmaxf(a.y + bc.y, 0.f);
            float sm = a.x + a.y, sq = a.x * a.x + a.y * a.y;
#pragma unroll
            for (int o = 16; o; o >>= 1) {
                sm += __shfl_xor_sync(0xffffffffu, sm, o);
                sq += __shfl_xor_sync(0xffffffffu, sq, o);
            }
            float mu = sm * (1.f / 64.f);
            float r = rsqrtf(sq * (1.f / 64.f) - mu * mu + 1e-5f);
            float2 v = make_float2((a.x - mu) * r * gg.x + bb.x,
                                   (a.y - mu) * r * gg.y + bb.y);
            int sw = (2 * lane) ^ (4 * (row & 7));   // XOR keeps pair adjacent
            *(float2*)&vs[row * 64 + sw] = v;
        }
    }

    // --- GEMM phase ---
    int g  = lane >> 2;            // fragment groupID (0..7)
    int tg = lane & 3;             // threadID in group (0..3)
    int h  = w >> 2;               // col-half (0/1)
    int Gr = 16 * (w & 3);         // warp row base

#pragma unroll
    for (int pass = 0; pass < 2; pass++) {
        int pb = pass * 64;
        __syncthreads();           // vs ready / prev pass frags consumed
        // stage + split W1 fragments: entry (ks,nbG,lane) = {B[k1][c],B[k1+4][c]}
        for (int i = t; i < 2048; i += 256) {
            int ks  = i >> 8;
            int nbG = (i >> 5) & 7;
            int ln  = i & 31;
            int k1  = ks * 8 + (ln & 3);
            int c   = pb + nbG * 8 + (ln >> 2);
            float bx = __ldg(&W1[k1 * 128 + c]);
            float by = __ldg(&W1[(k1 + 4) * 128 + c]);
            uint32_t hx, lx, hy, ly;
            tfsplit(bx, hx, lx);
            tfsplit(by, hy, ly);
            W1fh[i] = make_uint2(hx, hy);
            W1fl[i] = make_uint2(lx, ly);
        }
        __syncthreads();

        float acc[4][4];
#pragma unroll
        for (int nb = 0; nb < 4; nb++)
#pragma unroll
            for (int i = 0; i < 4; i++) acc[nb][i] = 0.f;

#pragma unroll
        for (int ks = 0; ks < 8; ks++) {
            int kc0 = (ks * 8 + tg)     ^ (4 * g);
            int kc1 = (ks * 8 + tg + 4) ^ (4 * g);
            float af0 = vs[(Gr + g) * 64 + kc0];      // (row g,   col t)
            float af1 = vs[(Gr + g + 8) * 64 + kc0];  // (row g+8, col t)
            float af2 = vs[(Gr + g) * 64 + kc1];      // (row g,   col t+4)
            float af3 = vs[(Gr + g + 8) * 64 + kc1];  // (row g+8, col t+4)
            uint32_t ah0, al0, ah1, al1, ah2, al2, ah3, al3;
            tfsplit(af0, ah0, al0);
            tfsplit(af1, ah1, al1);
            tfsplit(af2, ah2, al2);
            tfsplit(af3, ah3, al3);
#pragma unroll
            for (int nb = 0; nb < 4; nb++) {
                int fi = (ks * 8 + 4 * h + nb) * 32 + lane;
                uint2 bh = W1fh[fi];
                uint2 bl = W1fl[fi];
                mma_tf32(acc[nb], ah0, ah1, ah2, ah3, bh.x, bh.y);
                mma_tf32(acc[nb], ah0, ah1, ah2, ah3, bl.x, bl.y);
                mma_tf32(acc[nb], al0, al1, al2, al3, bh.x, bh.y);
            }
        }

        // epilogue: bias + relu + store (c0,c1)->row g, (c2,c3)->row g+8
#pragma unroll
        for (int nb = 0; nb < 4; nb++) {
            int col = pb + (4 * h + nb) * 8 + 2 * tg;
            float bx = __ldg(&b1[col]);
            float by = __ldg(&b1[col + 1]);
            int nA = node0 + Gr + g;
            int nB = nA + 8;
            if (nA < NN) {
                float2 o = make_float2(fmaxf(acc[nb][0] + bx, 0.f),
                                       fmaxf(acc[nb][1] + by, 0.f));
                *(float2*)&out[(size_t)nA * 128 + col] = o;
            }
            if (nB < NN) {
                float2 o = make_float2(fmaxf(acc[nb][2] + bx, 0.f),
                                       fmaxf(acc[nb][3] + by, 0.f));
                *(float2*)&out[(size_t)nB * 128 + col] = o;
            }
        }
    }
}

// ---------------- launch ----------------
extern "C" void kernel_launch(void* const* d_in, const int* in_sizes, int n_in,
                              void* d_out, int out_size) {
    const float* x      = (const float*)d_in[0];
    const int*   ei     = (const int*)d_in[1];     // int32
    const float* W_conv = (const float*)d_in[2];
    const float* b_conv = (const float*)d_in[3];
    const float* gamma  = (const float*)d_in[4];
    const float* beta   = (const float*)d_in[5];
    const float* W1     = (const float*)d_in[6];
    const float* b1     = (const float*)d_in[7];
    float* out = (float*)d_out;

    void* degp = nullptr;
    cudaGetSymbolAddress(&degp, g_deg);
    cudaMemsetAsync(degp, 0, NN * sizeof(int));

    long long n_h = (long long)NN * H2;            // 12,800,000
    long long rem = (long long)out_size - n_h;
    int mode = (rem >= (long long)4 * NE) ? 2 : (rem >= (long long)2 * NE) ? 1 : 0;

    k_deg_tail<<<((2 * NE / 4) + 255) / 256, 256>>>(ei, out + n_h, mode);
    k_gemm1<<<(NN + 63) / 64, 256>>>(x, W_conv);
    k_scatter<<<NE / (8 * 32), 256>>>(ei);         // 6250 blocks, exact
    k_epi<<<(NN + 63) / 64, 256>>>(b_conv, gamma, beta, W1, b1, out);
}

// round 12
// speedup vs baseline: 1.4998x; 1.0208x over previous
#include <cuda_runtime.h>
#include <cstdint>

#define NN   100000
#define NE   1600000
#define HID  64
#define H2   128
#define NSCB 98                       // ceil(NN/1024) scan blocks

typedef unsigned long long ull;

// ---------------- device scratch ----------------
__device__ __align__(16) float g_h0[(size_t)NN * HID];     // x @ W_conv
__device__ __align__(16) float g_agg[(size_t)NN * HID];    // aggregated
__device__ float g_dinv[NN];
__device__ int   g_deg[NN];
__device__ int   g_off[NN + 1];
__device__ int   g_cursor[NN];
__device__ int   g_bsum[128];
__device__ int   g_bsum2[128];
__device__ int   g_srcs[NE];

// ---------------- packed fp32x2 helpers (gemm1) ----------------
__device__ __forceinline__ ull fma2(ull a, ull b, ull c) {
    ull d;
    asm("fma.rn.f32x2 %0, %1, %2, %3;" : "=l"(d) : "l"(a), "l"(b), "l"(c));
    return d;
}
__device__ __forceinline__ ull pack2(float lo, float hi) {
    ull d;
    asm("mov.b64 %0, {%1, %2};" : "=l"(d) : "f"(lo), "f"(hi));
    return d;
}
__device__ __forceinline__ float lohisum(ull a) {
    float lo, hi;
    asm("mov.b64 {%0, %1}, %2;" : "=f"(lo), "=f"(hi) : "l"(a));
    return lo + hi;
}

// ---------------- tf32 mma helpers ----------------
__device__ __forceinline__ uint32_t f2tf(float x) {
    uint32_t r;
    asm("cvt.rna.tf32.f32 %0, %1;" : "=r"(r) : "f"(x));
    return r;
}
__device__ __forceinline__ void tfsplit(float x, uint32_t& hi, uint32_t& lo) {
    hi = f2tf(x);
    lo = f2tf(x - __uint_as_float(hi));
}
__device__ __forceinline__ void mma_tf32(float* c, uint32_t a0, uint32_t a1,
                                         uint32_t a2, uint32_t a3,
                                         uint32_t b0, uint32_t b1) {
    asm("mma.sync.aligned.m16n8k8.row.col.f32.tf32.tf32.f32 "
        "{%0,%1,%2,%3}, {%4,%5,%6,%7}, {%8,%9}, {%0,%1,%2,%3};"
        : "+f"(c[0]), "+f"(c[1]), "+f"(c[2]), "+f"(c[3])
        : "r"(a0), "r"(a1), "r"(a2), "r"(a3), "r"(b0), "r"(b1));
}

// ---------------- K1: degree + edge_index tail ----------------
__global__ void k_deg_tail(const int* __restrict__ ei, float* __restrict__ tail,
                           int mode) {
    int i4 = blockIdx.x * blockDim.x + threadIdx.x;
    if (i4 >= (2 * NE) / 4) return;
    int4 v = ((const int4*)ei)[i4];
    int base = i4 * 4;
    if (base >= NE) {
        atomicAdd(&g_deg[v.x], 1);
        atomicAdd(&g_deg[v.y], 1);
        atomicAdd(&g_deg[v.z], 1);
        atomicAdd(&g_deg[v.w], 1);
    }
    if (mode == 1) {
        float4 f = make_float4((float)v.x, (float)v.y, (float)v.z, (float)v.w);
        ((float4*)tail)[i4] = f;
    } else if (mode == 2) {
        longlong2 a = make_longlong2((long long)v.x, (long long)v.y);
        longlong2 b = make_longlong2((long long)v.z, (long long)v.w);
        ((longlong2*)tail)[i4 * 2]     = a;
        ((longlong2*)tail)[i4 * 2 + 1] = b;
    }
}

// ---------------- scan: exclusive prefix of deg -> off ----------------
__global__ void k_scan1() {
    __shared__ int ts[256];
    int b = blockIdx.x, t = threadIdx.x;
    int base = b * 1024 + t * 4;
    int v0 = (base + 0 < NN) ? g_deg[base + 0] : 0;
    int v1 = (base + 1 < NN) ? g_deg[base + 1] : 0;
    int v2 = (base + 2 < NN) ? g_deg[base + 2] : 0;
    int v3 = (base + 3 < NN) ? g_deg[base + 3] : 0;
    int s0 = v0, s1 = s0 + v1, s2 = s1 + v2, s3 = s2 + v3;
    ts[t] = s3;
    __syncthreads();
    for (int o = 1; o < 256; o <<= 1) {
        int x = 0;
        if (t >= o) x = ts[t - o];
        __syncthreads();
        if (t >= o) ts[t] += x;
        __syncthreads();
    }
    int excl = (t > 0) ? ts[t - 1] : 0;
    if (t == 255) g_bsum[b] = ts[255];
    if (base + 0 < NN) g_off[base + 0] = excl;
    if (base + 1 < NN) g_off[base + 1] = excl + s0;
    if (base + 2 < NN) g_off[base + 2] = excl + s1;
    if (base + 3 < NN) g_off[base + 3] = excl + s2;
}
__global__ void k_scan2() {
    __shared__ int ts[128];
    int t = threadIdx.x;
    ts[t] = (t < NSCB) ? g_bsum[t] : 0;
    __syncthreads();
    for (int o = 1; o < 128; o <<= 1) {
        int x = 0;
        if (t >= o) x = ts[t - o];
        __syncthreads();
        if (t >= o) ts[t] += x;
        __syncthreads();
    }
    g_bsum2[t] = (t > 0) ? ts[t - 1] : 0;
}
__global__ void k_scan3() {
    int i = blockIdx.x * blockDim.x + threadIdx.x;
    if (i < NN) {
        int v = g_off[i] + g_bsum2[i >> 10];
        g_off[i] = v;
        g_cursor[i] = v;
    }
    if (i == 0) g_off[NN] = NE;
}

// ---------------- K: bucket edges by dst ----------------
__global__ void k_bucket(const int* __restrict__ ei) {
    int e = blockIdx.x * blockDim.x + threadIdx.x;
    if (e < NE) {
        int src = ei[e];
        int dst = ei[NE + e];
        int pos = atomicAdd(&g_cursor[dst], 1);
        g_srcs[pos] = src;
    }
}

// ---------------- K2: gemm1 (h0 + dinv; agg write dropped) ----------------
__global__ void k_gemm1(const float* __restrict__ x, const float* __restrict__ W) {
    __shared__ __align__(16) ull Wp[32 * 64];
    __shared__ __align__(16) ull xp[64 * 34];

    int t = threadIdx.x;
    for (int i = t; i < 32 * 64; i += 256) {
        int tt = i >> 6, c = i & 63;
        Wp[i] = pack2(W[(2 * tt) * 64 + c], W[(2 * tt + 1) * 64 + c]);
    }
    int row0 = blockIdx.x * 64;
    for (int i = t; i < 64 * 16; i += 256) {
        int r = i >> 4, c4 = i & 15;
        int gr = row0 + r;
        float4 v = make_float4(0.f, 0.f, 0.f, 0.f);
        if (gr < NN) v = ((const float4*)x)[(size_t)gr * 16 + c4];
        xp[r * 34 + 2 * c4]     = pack2(v.x, v.y);
        xp[r * 34 + 2 * c4 + 1] = pack2(v.z, v.w);
    }
    __syncthreads();

    int tx = t & 15, ty = t >> 4;
    ull acc[4][4];
#pragma unroll
    for (int i = 0; i < 4; i++)
#pragma unroll
        for (int j = 0; j < 4; j++) acc[i][j] = 0ull;

#pragma unroll 8
    for (int tt = 0; tt < 32; tt++) {
        ulonglong2 wA = *(const ulonglong2*)&Wp[tt * 64 + 2 * tx];
        ulonglong2 wB = *(const ulonglong2*)&Wp[tt * 64 + 32 + 2 * tx];
#pragma unroll
        for (int i = 0; i < 4; i++) {
            ull xv = xp[(4 * ty + i) * 34 + tt];
            acc[i][0] = fma2(xv, wA.x, acc[i][0]);
            acc[i][1] = fma2(xv, wA.y, acc[i][1]);
            acc[i][2] = fma2(xv, wB.x, acc[i][2]);
            acc[i][3] = fma2(xv, wB.y, acc[i][3]);
        }
    }

#pragma unroll
    for (int i = 0; i < 4; i++) {
        int gr = row0 + 4 * ty + i;
        if (gr < NN) {
            float d = rsqrtf((float)g_deg[gr] + 1.0f);
            if (tx == 0) g_dinv[gr] = d;
            float2 oA = make_float2(lohisum(acc[i][0]), lohisum(acc[i][1]));
            float2 oB = make_float2(lohisum(acc[i][2]), lohisum(acc[i][3]));
            ((float2*)g_h0)[(size_t)gr * 32 + tx]      = oA;
            ((float2*)g_h0)[(size_t)gr * 32 + 16 + tx] = oB;
        }
    }
}

// ---------------- K3: per-node gather-aggregate (no atomics) ----------------
// One warp per node. acc starts at self-loop term h0[n]*dinv[n]^2; srcs are
// chunk-loaded by lanes and shfl-broadcast; gathers are 256B contiguous.
__global__ void k_agg() {
    int gw = (blockIdx.x * blockDim.x + threadIdx.x) >> 5;
    if (gw >= NN) return;
    int lane = threadIdx.x & 31;
    int n = gw;
    float dn = g_dinv[n];
    float2 acc = ((const float2*)g_h0)[(size_t)n * 32 + lane];
    float n2 = dn * dn;
    acc.x *= n2;
    acc.y *= n2;

    int o0 = g_off[n], o1 = g_off[n + 1];
    for (int base = o0; base < o1; base += 32) {
        int idx = base + lane;
        int s = 0;
        float dv = 0.f;
        if (idx < o1) {
            s = g_srcs[idx];
            dv = __ldg(&g_dinv[s]);
        }
        int cnt = min(32, o1 - base);
        for (int j = 0; j < cnt; j++) {
            int   sj = __shfl_sync(0xffffffffu, s, j);
            float nj = __shfl_sync(0xffffffffu, dv, j) * dn;
            float2 v = ((const float2*)g_h0)[(size_t)sj * 32 + lane];
            acc.x += v.x * nj;
            acc.y += v.y * nj;
        }
    }
    ((float2*)g_agg)[(size_t)n * 32 + lane] = acc;
}

// ---------------- K4: bias+ReLU+LN + tensor GEMM2 (unchanged R11) -----------
__global__ void __launch_bounds__(256) k_epi(
        const float* __restrict__ bconv, const float* __restrict__ gamma,
        const float* __restrict__ beta, const float* __restrict__ W1,
        const float* __restrict__ b1, float* __restrict__ out) {
    __shared__ __align__(16) float vs[64 * 64];
    __shared__ __align__(16) uint2 W1fh[8 * 8 * 32];
    __shared__ __align__(16) uint2 W1fl[8 * 8 * 32];

    int t = threadIdx.x, lane = t & 31, w = t >> 5;
    int node0 = blockIdx.x * 64;

    if (node0 + 64 > NN) {
        for (int i = t; i < 64 * 64; i += 256) vs[i] = 0.f;
        __syncthreads();
    }

    float2 bc = __ldg((const float2*)bconv + lane);
    float2 gg = __ldg((const float2*)gamma + lane);
    float2 bb = __ldg((const float2*)beta + lane);

#pragma unroll
    for (int s = 0; s < 8; s++) {
        int row = 8 * w + s;
        int node = node0 + row;
        if (node < NN) {
            float2 a = ((const float2*)g_agg)[(size_t)node * 32 + lane];
            a.x = fmaxf(a.x + bc.x, 0.f);
            a.y = fmaxf(a.y + bc.y, 0.f);
            float sm = a.x + a.y, sq = a.x * a.x + a.y * a.y;
#pragma unroll
            for (int o = 16; o; o >>= 1) {
                sm += __shfl_xor_sync(0xffffffffu, sm, o);
                sq += __shfl_xor_sync(0xffffffffu, sq, o);
            }
            float mu = sm * (1.f / 64.f);
            float r = rsqrtf(sq * (1.f / 64.f) - mu * mu + 1e-5f);
            float2 v = make_float2((a.x - mu) * r * gg.x + bb.x,
                                   (a.y - mu) * r * gg.y + bb.y);
            int sw = (2 * lane) ^ (4 * (row & 7));
            *(float2*)&vs[row * 64 + sw] = v;
        }
    }

    int g  = lane >> 2;
    int tg = lane & 3;
    int h  = w >> 2;
    int Gr = 16 * (w & 3);

#pragma unroll
    for (int pass = 0; pass < 2; pass++) {
        int pb = pass * 64;
        __syncthreads();
        for (int i = t; i < 2048; i += 256) {
            int ks  = i >> 8;
            int nbG = (i >> 5) & 7;
            int ln  = i & 31;
            int k1  = ks * 8 + (ln & 3);
            int c   = pb + nbG * 8 + (ln >> 2);
            float bx = __ldg(&W1[k1 * 128 + c]);
            float by = __ldg(&W1[(k1 + 4) * 128 + c]);
            uint32_t hx, lx, hy, ly;
            tfsplit(bx, hx, lx);
            tfsplit(by, hy, ly);
            W1fh[i] = make_uint2(hx, hy);
            W1fl[i] = make_uint2(lx, ly);
        }
        __syncthreads();

        float acc[4][4];
#pragma unroll
        for (int nb = 0; nb < 4; nb++)
#pragma unroll
            for (int i = 0; i < 4; i++) acc[nb][i] = 0.f;

#pragma unroll
        for (int ks = 0; ks < 8; ks++) {
            int kc0 = (ks * 8 + tg)     ^ (4 * g);
            int kc1 = (ks * 8 + tg + 4) ^ (4 * g);
            float af0 = vs[(Gr + g) * 64 + kc0];
            float af1 = vs[(Gr + g + 8) * 64 + kc0];
            float af2 = vs[(Gr + g) * 64 + kc1];
            float af3 = vs[(Gr + g + 8) * 64 + kc1];
            uint32_t ah0, al0, ah1, al1, ah2, al2, ah3, al3;
            tfsplit(af0, ah0, al0);
            tfsplit(af1, ah1, al1);
            tfsplit(af2, ah2, al2);
            tfsplit(af3, ah3, al3);
#pragma unroll
            for (int nb = 0; nb < 4; nb++) {
                int fi = (ks * 8 + 4 * h + nb) * 32 + lane;
                uint2 bh = W1fh[fi];
                uint2 bl = W1fl[fi];
                mma_tf32(acc[nb], ah0, ah1, ah2, ah3, bh.x, bh.y);
                mma_tf32(acc[nb], ah0, ah1, ah2, ah3, bl.x, bl.y);
                mma_tf32(acc[nb], al0, al1, al2, al3, bh.x, bh.y);
            }
        }

#pragma unroll
        for (int nb = 0; nb < 4; nb++) {
            int col = pb + (4 * h + nb) * 8 + 2 * tg;
            float bx = __ldg(&b1[col]);
            float by = __ldg(&b1[col + 1]);
            int nA = node0 + Gr + g;
            int nB = nA + 8;
            if (nA < NN) {
                float2 o = make_float2(fmaxf(acc[nb][0] + bx, 0.f),
                                       fmaxf(acc[nb][1] + by, 0.f));
                *(float2*)&out[(size_t)nA * 128 + col] = o;
            }
            if (nB < NN) {
                float2 o = make_float2(fmaxf(acc[nb][2] + bx, 0.f),
                                       fmaxf(acc[nb][3] + by, 0.f));
                *(float2*)&out[(size_t)nB * 128 + col] = o;
            }
        }
    }
}

// ---------------- launch ----------------
extern "C" void kernel_launch(void* const* d_in, const int* in_sizes, int n_in,
                              void* d_out, int out_size) {
    const float* x      = (const float*)d_in[0];
    const int*   ei     = (const int*)d_in[1];     // int32
    const float* W_conv = (const float*)d_in[2];
    const float* b_conv = (const float*)d_in[3];
    const float* gamma  = (const float*)d_in[4];
    const float* beta   = (const float*)d_in[5];
    const float* W1     = (const float*)d_in[6];
    const float* b1     = (const float*)d_in[7];
    float* out = (float*)d_out;

    void* degp = nullptr;
    cudaGetSymbolAddress(&degp, g_deg);
    cudaMemsetAsync(degp, 0, NN * sizeof(int));

    long long n_h = (long long)NN * H2;
    long long rem = (long long)out_size - n_h;
    int mode = (rem >= (long long)4 * NE) ? 2 : (rem >= (long long)2 * NE) ? 1 : 0;

    k_deg_tail<<<((2 * NE / 4) + 255) / 256, 256>>>(ei, out + n_h, mode);
    k_scan1<<<NSCB, 256>>>();
    k_scan2<<<1, 128>>>();
    k_scan3<<<(NN + 255) / 256, 256>>>();
    k_gemm1<<<(NN + 63) / 64, 256>>>(x, W_conv);
    k_bucket<<<(NE + 255) / 256, 256>>>(ei);
    k_agg<<<(NN * 32 + 255) / 256, 256>>>();
    k_epi<<<(NN + 63) / 64, 256>>>(b_conv, gamma, beta, W1, b1, out);
}

// round 13
// speedup vs baseline: 1.6362x; 1.0909x over previous
#include <cuda_runtime.h>
#include <cstdint>

#define NN   100000
#define NE   1600000
#define HID  64
#define H2   128
#define NSCB 98                       // ceil(NN/1024) scan blocks

typedef unsigned long long ull;

// ---------------- device scratch ----------------
__device__ __align__(16) float g_h0[(size_t)NN * HID];     // x @ W_conv
__device__ __align__(16) float g_agg[(size_t)NN * HID];    // aggregated
__device__ float g_dinv[NN];
__device__ int   g_deg[NN];
__device__ int   g_off[NN];
__device__ int   g_cursor[NN];
__device__ int   g_base;
__device__ int   g_srcs[NE];

// ---------------- packed fp32x2 helpers (gemm1) ----------------
__device__ __forceinline__ ull fma2(ull a, ull b, ull c) {
    ull d;
    asm("fma.rn.f32x2 %0, %1, %2, %3;" : "=l"(d) : "l"(a), "l"(b), "l"(c));
    return d;
}
__device__ __forceinline__ ull pack2(float lo, float hi) {
    ull d;
    asm("mov.b64 %0, {%1, %2};" : "=l"(d) : "f"(lo), "f"(hi));
    return d;
}
__device__ __forceinline__ float lohisum(ull a) {
    float lo, hi;
    asm("mov.b64 {%0, %1}, %2;" : "=f"(lo), "=f"(hi) : "l"(a));
    return lo + hi;
}

// ---------------- tf32 mma helpers ----------------
__device__ __forceinline__ uint32_t f2tf(float x) {
    uint32_t r;
    asm("cvt.rna.tf32.f32 %0, %1;" : "=r"(r) : "f"(x));
    return r;
}
__device__ __forceinline__ void tfsplit(float x, uint32_t& hi, uint32_t& lo) {
    hi = f2tf(x);
    lo = f2tf(x - __uint_as_float(hi));
}
__device__ __forceinline__ void mma_tf32(float* c, uint32_t a0, uint32_t a1,
                                         uint32_t a2, uint32_t a3,
                                         uint32_t b0, uint32_t b1) {
    asm("mma.sync.aligned.m16n8k8.row.col.f32.tf32.tf32.f32 "
        "{%0,%1,%2,%3}, {%4,%5,%6,%7}, {%8,%9}, {%0,%1,%2,%3};"
        : "+f"(c[0]), "+f"(c[1]), "+f"(c[2]), "+f"(c[3])
        : "r"(a0), "r"(a1), "r"(a2), "r"(a3), "r"(b0), "r"(b1));
}

// ---------------- K1: degree + edge_index tail ----------------
__global__ void k_deg_tail(const int* __restrict__ ei, float* __restrict__ tail,
                           int mode) {
    int i4 = blockIdx.x * blockDim.x + threadIdx.x;
    if (i4 == 0) g_base = 0;                           // reset for this launch
    if (i4 >= (2 * NE) / 4) return;
    int4 v = ((const int4*)ei)[i4];
    int base = i4 * 4;
    if (base >= NE) {
        atomicAdd(&g_deg[v.x], 1);
        atomicAdd(&g_deg[v.y], 1);
        atomicAdd(&g_deg[v.z], 1);
        atomicAdd(&g_deg[v.w], 1);
    }
    if (mode == 1) {
        float4 f = make_float4((float)v.x, (float)v.y, (float)v.z, (float)v.w);
        ((float4*)tail)[i4] = f;
    } else if (mode == 2) {
        longlong2 a = make_longlong2((long long)v.x, (long long)v.y);
        longlong2 b = make_longlong2((long long)v.z, (long long)v.w);
        ((longlong2*)tail)[i4 * 2]     = a;
        ((longlong2*)tail)[i4 * 2 + 1] = b;
    }
}

// ---------------- single-kernel scan: disjoint bucket bases -----------------
// Block-internal exclusive scan; block base via atomicAdd (arrival order is
// fine: k_agg uses off[n]+deg[n], so ranges only need to be disjoint).
__global__ void k_scan() {
    __shared__ int ts[256];
    __shared__ int sbase;
    int b = blockIdx.x, t = threadIdx.x;
    int base = b * 1024 + t * 4;
    int v0 = (base + 0 < NN) ? g_deg[base + 0] : 0;
    int v1 = (base + 1 < NN) ? g_deg[base + 1] : 0;
    int v2 = (base + 2 < NN) ? g_deg[base + 2] : 0;
    int v3 = (base + 3 < NN) ? g_deg[base + 3] : 0;
    int s0 = v0, s1 = s0 + v1, s2 = s1 + v2, s3 = s2 + v3;
    ts[t] = s3;
    __syncthreads();
    for (int o = 1; o < 256; o <<= 1) {
        int x = 0;
        if (t >= o) x = ts[t - o];
        __syncthreads();
        if (t >= o) ts[t] += x;
        __syncthreads();
    }
    if (t == 0) sbase = atomicAdd(&g_base, ts[255]);
    __syncthreads();
    int excl = sbase + ((t > 0) ? ts[t - 1] : 0);
    if (base + 0 < NN) { g_off[base + 0] = excl;      g_cursor[base + 0] = excl; }
    if (base + 1 < NN) { g_off[base + 1] = excl + s0; g_cursor[base + 1] = excl + s0; }
    if (base + 2 < NN) { g_off[base + 2] = excl + s1; g_cursor[base + 2] = excl + s1; }
    if (base + 3 < NN) { g_off[base + 3] = excl + s2; g_cursor[base + 3] = excl + s2; }
}

// ---------------- K: bucket edges by dst ----------------
__global__ void k_bucket(const int* __restrict__ ei) {
    int e = blockIdx.x * blockDim.x + threadIdx.x;
    if (e < NE) {
        int src = ei[e];
        int dst = ei[NE + e];
        int pos = atomicAdd(&g_cursor[dst], 1);
        g_srcs[pos] = src;
    }
}

// ---------------- K2: gemm1 (h0 + dinv) ----------------
__global__ void k_gemm1(const float* __restrict__ x, const float* __restrict__ W) {
    __shared__ __align__(16) ull Wp[32 * 64];
    __shared__ __align__(16) ull xp[64 * 34];

    int t = threadIdx.x;
    for (int i = t; i < 32 * 64; i += 256) {
        int tt = i >> 6, c = i & 63;
        Wp[i] = pack2(W[(2 * tt) * 64 + c], W[(2 * tt + 1) * 64 + c]);
    }
    int row0 = blockIdx.x * 64;
    for (int i = t; i < 64 * 16; i += 256) {
        int r = i >> 4, c4 = i & 15;
        int gr = row0 + r;
        float4 v = make_float4(0.f, 0.f, 0.f, 0.f);
        if (gr < NN) v = ((const float4*)x)[(size_t)gr * 16 + c4];
        xp[r * 34 + 2 * c4]     = pack2(v.x, v.y);
        xp[r * 34 + 2 * c4 + 1] = pack2(v.z, v.w);
    }
    __syncthreads();

    int tx = t & 15, ty = t >> 4;
    ull acc[4][4];
#pragma unroll
    for (int i = 0; i < 4; i++)
#pragma unroll
        for (int j = 0; j < 4; j++) acc[i][j] = 0ull;

#pragma unroll 8
    for (int tt = 0; tt < 32; tt++) {
        ulonglong2 wA = *(const ulonglong2*)&Wp[tt * 64 + 2 * tx];
        ulonglong2 wB = *(const ulonglong2*)&Wp[tt * 64 + 32 + 2 * tx];
#pragma unroll
        for (int i = 0; i < 4; i++) {
            ull xv = xp[(4 * ty + i) * 34 + tt];
            acc[i][0] = fma2(xv, wA.x, acc[i][0]);
            acc[i][1] = fma2(xv, wA.y, acc[i][1]);
            acc[i][2] = fma2(xv, wB.x, acc[i][2]);
            acc[i][3] = fma2(xv, wB.y, acc[i][3]);
        }
    }

#pragma unroll
    for (int i = 0; i < 4; i++) {
        int gr = row0 + 4 * ty + i;
        if (gr < NN) {
            float d = rsqrtf((float)g_deg[gr] + 1.0f);
            if (tx == 0) g_dinv[gr] = d;
            float2 oA = make_float2(lohisum(acc[i][0]), lohisum(acc[i][1]));
            float2 oB = make_float2(lohisum(acc[i][2]), lohisum(acc[i][3]));
            ((float2*)g_h0)[(size_t)gr * 32 + tx]      = oA;
            ((float2*)g_h0)[(size_t)gr * 32 + 16 + tx] = oB;
        }
    }
}

// ---------------- K3: per-node gather-aggregate, MLP=4 ----------------------
// One warp per node; edges in groups of 4 with all 4 gathers issued before
// the accumulates. Lanes beyond cnt carry (s=n, w=0): over-reads add 0.
__global__ void __launch_bounds__(256) k_agg() {
    int gw = (blockIdx.x * blockDim.x + threadIdx.x) >> 5;
    if (gw >= NN) return;
    int lane = threadIdx.x & 31;
    int n = gw;
    float dn = g_dinv[n];
    float2 acc = ((const float2*)g_h0)[(size_t)n * 32 + lane];
    float n2 = dn * dn;
    acc.x *= n2;
    acc.y *= n2;

    int o0 = g_off[n];
    int deg = g_deg[n];
    for (int base = 0; base < deg; base += 32) {
        int s = n;
        float wgt = 0.f;
        if (base + lane < deg) {
            s = g_srcs[o0 + base + lane];
            wgt = __ldg(&g_dinv[s]) * dn;
        }
        int cnt = min(32, deg - base);
        for (int j = 0; j < cnt; j += 4) {
            int   s0 = __shfl_sync(0xffffffffu, s, j);
            int   s1 = __shfl_sync(0xffffffffu, s, j + 1);
            int   s2 = __shfl_sync(0xffffffffu, s, j + 2);
            int   s3 = __shfl_sync(0xffffffffu, s, j + 3);
            float n0 = __shfl_sync(0xffffffffu, wgt, j);
            float n1 = __shfl_sync(0xffffffffu, wgt, j + 1);
            float n2_ = __shfl_sync(0xffffffffu, wgt, j + 2);
            float n3 = __shfl_sync(0xffffffffu, wgt, j + 3);
            float2 v0 = ((const float2*)g_h0)[(size_t)s0 * 32 + lane];
            float2 v1 = ((const float2*)g_h0)[(size_t)s1 * 32 + lane];
            float2 v2 = ((const float2*)g_h0)[(size_t)s2 * 32 + lane];
            float2 v3 = ((const float2*)g_h0)[(size_t)s3 * 32 + lane];
            acc.x += v0.x * n0; acc.y += v0.y * n0;
            acc.x += v1.x * n1; acc.y += v1.y * n1;
            acc.x += v2.x * n2_; acc.y += v2.y * n2_;
            acc.x += v3.x * n3; acc.y += v3.y * n3;
        }
    }
    ((float2*)g_agg)[(size_t)n * 32 + lane] = acc;
}

// ---------------- K4: bias+ReLU+LN + tensor GEMM2 (unchanged R11) -----------
__global__ void __launch_bounds__(256) k_epi(
        const float* __restrict__ bconv, const float* __restrict__ gamma,
        const float* __restrict__ beta, const float* __restrict__ W1,
        const float* __restrict__ b1, float* __restrict__ out) {
    __shared__ __align__(16) float vs[64 * 64];
    __shared__ __align__(16) uint2 W1fh[8 * 8 * 32];
    __shared__ __align__(16) uint2 W1fl[8 * 8 * 32];

    int t = threadIdx.x, lane = t & 31, w = t >> 5;
    int node0 = blockIdx.x * 64;

    if (node0 + 64 > NN) {
        for (int i = t; i < 64 * 64; i += 256) vs[i] = 0.f;
        __syncthreads();
    }

    float2 bc = __ldg((const float2*)bconv + lane);
    float2 gg = __ldg((const float2*)gamma + lane);
    float2 bb = __ldg((const float2*)beta + lane);

#pragma unroll
    for (int s = 0; s < 8; s++) {
        int row = 8 * w + s;
        int node = node0 + row;
        if (node < NN) {
            float2 a = ((const float2*)g_agg)[(size_t)node * 32 + lane];
            a.x = fmaxf(a.x + bc.x, 0.f);
            a.y = fmaxf(a.y + bc.y, 0.f);
            float sm = a.x + a.y, sq = a.x * a.x + a.y * a.y;
#pragma unroll
            for (int o = 16; o; o >>= 1) {
                sm += __shfl_xor_sync(0xffffffffu, sm, o);
                sq += __shfl_xor_sync(0xffffffffu, sq, o);
            }
            float mu = sm * (1.f / 64.f);
            float r = rsqrtf(sq * (1.f / 64.f) - mu * mu + 1e-5f);
            float2 v = make_float2((a.x - mu) * r * gg.x + bb.x,
                                   (a.y - mu) * r * gg.y + bb.y);
            int sw = (2 * lane) ^ (4 * (row & 7));
            *(float2*)&vs[row * 64 + sw] = v;
        }
    }

    int g  = lane >> 2;
    int tg = lane & 3;
    int h  = w >> 2;
    int Gr = 16 * (w & 3);

#pragma unroll
    for (int pass = 0; pass < 2; pass++) {
        int pb = pass * 64;
        __syncthreads();
        for (int i = t; i < 2048; i += 256) {
            int ks  = i >> 8;
            int nbG = (i >> 5) & 7;
            int ln  = i & 31;
            int k1  = ks * 8 + (ln & 3);
            int c   = pb + nbG * 8 + (ln >> 2);
            float bx = __ldg(&W1[k1 * 128 + c]);
            float by = __ldg(&W1[(k1 + 4) * 128 + c]);
            uint32_t hx, lx, hy, ly;
            tfsplit(bx, hx, lx);
            tfsplit(by, hy, ly);
            W1fh[i] = make_uint2(hx, hy);
            W1fl[i] = make_uint2(lx, ly);
        }
        __syncthreads();

        float acc[4][4];
#pragma unroll
        for (int nb = 0; nb < 4; nb++)
#pragma unroll
            for (int i = 0; i < 4; i++) acc[nb][i] = 0.f;

#pragma unroll
        for (int ks = 0; ks < 8; ks++) {
            int kc0 = (ks * 8 + tg)     ^ (4 * g);
            int kc1 = (ks * 8 + tg + 4) ^ (4 * g);
            float af0 = vs[(Gr + g) * 64 + kc0];
            float af1 = vs[(Gr + g + 8) * 64 + kc0];
            float af2 = vs[(Gr + g) * 64 + kc1];
            float af3 = vs[(Gr + g + 8) * 64 + kc1];
            uint32_t ah0, al0, ah1, al1, ah2, al2, ah3, al3;
            tfsplit(af0, ah0, al0);
            tfsplit(af1, ah1, al1);
            tfsplit(af2, ah2, al2);
            tfsplit(af3, ah3, al3);
#pragma unroll
            for (int nb = 0; nb < 4; nb++) {
                int fi = (ks * 8 + 4 * h + nb) * 32 + lane;
                uint2 bh = W1fh[fi];
                uint2 bl = W1fl[fi];
                mma_tf32(acc[nb], ah0, ah1, ah2, ah3, bh.x, bh.y);
                mma_tf32(acc[nb], ah0, ah1, ah2, ah3, bl.x, bl.y);
                mma_tf32(acc[nb], al0, al1, al2, al3, bh.x, bh.y);
            }
        }

#pragma unroll
        for (int nb = 0; nb < 4; nb++) {
            int col = pb + (4 * h + nb) * 8 + 2 * tg;
            float bx = __ldg(&b1[col]);
            float by = __ldg(&b1[col + 1]);
            int nA = node0 + Gr + g;
            int nB = nA + 8;
            if (nA < NN) {
                float2 o = make_float2(fmaxf(acc[nb][0] + bx, 0.f),
                                       fmaxf(acc[nb][1] + by, 0.f));
                *(float2*)&out[(size_t)nA * 128 + col] = o;
            }
            if (nB < NN) {
                float2 o = make_float2(fmaxf(acc[nb][2] + bx, 0.f),
                                       fmaxf(acc[nb][3] + by, 0.f));
                *(float2*)&out[(size_t)nB * 128 + col] = o;
            }
        }
    }
}

// ---------------- launch ----------------
extern "C" void kernel_launch(void* const* d_in, const int* in_sizes, int n_in,
                              void* d_out, int out_size) {
    const float* x      = (const float*)d_in[0];
    const int*   ei     = (const int*)d_in[1];     // int32
    const float* W_conv = (const float*)d_in[2];
    const float* b_conv = (const float*)d_in[3];
    const float* gamma  = (const float*)d_in[4];
    const float* beta   = (const float*)d_in[5];
    const float* W1     = (const float*)d_in[6];
    const float* b1     = (const float*)d_in[7];
    float* out = (float*)d_out;

    void* degp = nullptr;
    cudaGetSymbolAddress(&degp, g_deg);
    cudaMemsetAsync(degp, 0, NN * sizeof(int));

    long long n_h = (long long)NN * H2;
    long long rem = (long long)out_size - n_h;
    int mode = (rem >= (long long)4 * NE) ? 2 : (rem >= (long long)2 * NE) ? 1 : 0;

    k_deg_tail<<<((2 * NE / 4) + 255) / 256, 256>>>(ei, out + n_h, mode);
    k_scan<<<NSCB, 256>>>();
    k_gemm1<<<(NN + 63) / 64, 256>>>(x, W_conv);
    k_bucket<<<(NE + 255) / 256, 256>>>(ei);
    k_agg<<<(NN * 32 + 255) / 256, 256>>>();
    k_epi<<<(NN + 63) / 64, 256>>>(b_conv, gamma, beta, W1, b1, out);
}